// round 12
// baseline (speedup 1.0000x reference)
#include <cuda_runtime.h>
#include <cuda_fp16.h>
#include <math.h>
#include <cstdint>

// Problem dims
#define MROWS 16384   // B*T = 4*4096
#define DDIM  1024
#define TLEN  4096
#define CHUNKS 32
#define CHLEN  (TLEN / CHUNKS)   // 128
#define NCHAIN 4096              // B * D

// ---------------- scratch (device globals; no allocation allowed) ----------
__device__ float g_res[MROWS * DDIM];
__device__ __half g_hl [MROWS * DDIM];
__device__ __half g_Af  [MROWS * DDIM];
__device__ __half g_Af2 [MROWS * DDIM];
__device__ __half g_rt16[MROWS * DDIM];
__device__ __half g_it16[MROWS * DDIM];
__device__ __half g_Wf [8 * DDIM * DDIM];   // 8 weight slots
__device__ float g_Acar[NCHAIN * CHUNKS];
__device__ float g_Hcar[NCHAIN * CHUNKS];
__device__ float g_carry[NCHAIN * CHUNKS];

// ---------------- base-ISA tensor helpers ----------------------------------
__device__ __forceinline__ uint32_t smem_to_u32(const void* p) {
    uint32_t a;
    asm("{ .reg .u64 t; cvta.to.shared.u64 t, %1; cvt.u32.u64 %0, t; }"
        : "=r"(a) : "l"(p));
    return a;
}
__device__ __forceinline__ void cpasync16(uint32_t dst, const void* src) {
    asm volatile("cp.async.cg.shared.global [%0], [%1], 16;"
                 :: "r"(dst), "l"(src) : "memory");
}
#define CP_COMMIT() asm volatile("cp.async.commit_group;" ::: "memory")
#define CP_WAIT(n)  asm volatile("cp.async.wait_group %0;" :: "n"(n) : "memory")

__device__ __forceinline__ void ldsm4(uint32_t addr, uint32_t* r) {
    asm volatile("ldmatrix.sync.aligned.m8n8.x4.shared.b16 {%0,%1,%2,%3}, [%4];"
                 : "=r"(r[0]), "=r"(r[1]), "=r"(r[2]), "=r"(r[3]) : "r"(addr));
}
__device__ __forceinline__ void mma16816h(float* c, const uint32_t* a, const uint32_t* b) {
    asm volatile(
        "mma.sync.aligned.m16n8k16.row.col.f32.f16.f16.f32 "
        "{%0,%1,%2,%3}, {%4,%5,%6,%7}, {%8,%9}, {%0,%1,%2,%3};"
        : "+f"(c[0]), "+f"(c[1]), "+f"(c[2]), "+f"(c[3])
        : "r"(a[0]), "r"(a[1]), "r"(a[2]), "r"(a[3]), "r"(b[0]), "r"(b[1]));
}

// ---------------- math helpers ---------------------------------------------
__device__ __forceinline__ float gelu_exact(float x) {
    return 0.5f * x * (1.0f + erff(x * 0.70710678118654752440f));
}
__device__ __forceinline__ float sigmoidf_(float x) {
    return 1.0f / (1.0f + expf(-x));
}

// ---------------- fp32 -> fp16 convert: all 8 weights in one launch --------
__global__ void conv_all_w_kernel(const float* __restrict__ w0, const float* __restrict__ w1,
                                  const float* __restrict__ w2, const float* __restrict__ w3,
                                  const float* __restrict__ w4, const float* __restrict__ w5,
                                  const float* __restrict__ w6, const float* __restrict__ w7,
                                  __half* __restrict__ dst) {
    const float* srcs[8] = {w0, w1, w2, w3, w4, w5, w6, w7};
    int slot = blockIdx.y;
    const float* src = srcs[slot];
    __half* d = dst + (size_t)slot * DDIM * DDIM;
    int i = blockIdx.x * 256 + threadIdx.x;       // 0 .. DDIM*DDIM/4-1
    float4 v = ((const float4*)src)[i];
    ((__half2*)d)[2 * i]     = __floats2half2_rn(v.x, v.y);
    ((__half2*)d)[2 * i + 1] = __floats2half2_rn(v.z, v.w);
}

// ---------------- fp16 1-term mma.sync GEMM, BN=128, 3-stage ---------------
// CTA tile 128x128, K-chunk 64, 3-stage cp.async, 256 threads, 2 CTAs/SM.
// Warp grid 4(M) x 2(N), warp tile 32x64.
// N = 1024 (single) or 2048 (double: cols>=1024 -> bias2/C2/Sf2).
#define F_TILE_A 16384               // 128 x 64 fp16
#define F_TILE_B 16384               // 128 x 64 fp16
#define F_STAGE  32768
#define NSTAGE 3
#define NCHUNK (DDIM / 64)           // 16

__device__ __forceinline__ uint32_t swaddr(uint32_t tile, uint32_t row, uint32_t kb) {
    uint32_t off = row * 128u + kb;
    return tile + (off ^ ((off >> 3) & 0x70u));
}

__global__ void __launch_bounds__(256, 2)
fgemm_kernel(const __half* __restrict__ Af, const __half* __restrict__ Bf,
             const float* __restrict__ bias, const float* __restrict__ addp,
             float* __restrict__ C, int doAdd,
             __half* __restrict__ Sf,
             const float* __restrict__ bias2, float* __restrict__ C2,
             __half* __restrict__ Sf2) {
    extern __shared__ __align__(1024) char smem_raw[];
    uint32_t smem0 = smem_to_u32(smem_raw);
    uint32_t tbase = (smem0 + 1023u) & ~1023u;

    int tid = threadIdx.x;
    int wid = tid >> 5;
    int lane = tid & 31;
    int m0 = blockIdx.y * 128;
    int n0 = blockIdx.x * 128;

    // ---- producer mapping: 8 x 16B vecs per thread per stage ----
    int row_base = tid >> 3;        // 0..31
    int col = tid & 7;
    const char* srcb[8];
    uint32_t stsoff[8];
    {
        const char* aB = (const char*)(Af + (size_t)m0 * DDIM);
        const char* bB = (const char*)(Bf + (size_t)n0 * DDIM);
        #pragma unroll
        for (int i = 0; i < 4; i++) {
            uint32_t rr = (uint32_t)row_base + 32u * i;
            srcb[i] = aB + (size_t)rr * 2048 + col * 16;
            uint32_t off = rr * 128u + (uint32_t)col * 16u;
            stsoff[i] = off ^ ((off >> 3) & 0x70u);
        }
        #pragma unroll
        for (int i = 4; i < 8; i++) {
            uint32_t rr = (uint32_t)row_base + 32u * (i - 4);
            srcb[i] = bB + (size_t)rr * 2048 + col * 16;
            uint32_t off = rr * 128u + (uint32_t)col * 16u;
            stsoff[i] = F_TILE_A + (off ^ ((off >> 3) & 0x70u));
        }
    }

    #define F_ISSUE(buf, chunk) do { \
        uint32_t db_ = tbase + (uint32_t)(buf) * F_STAGE; \
        _Pragma("unroll") \
        for (int i_ = 0; i_ < 8; i_++) \
            cpasync16(db_ + stsoff[i_], srcb[i_] + (size_t)(chunk) * 128); \
        CP_COMMIT(); \
    } while (0)

    // ---- consumer mapping: 8 warps, warp tile 32x64 (4 M x 2 N) ----
    int warp_m = wid & 3;
    int warp_n = wid >> 2;          // 0..1
    uint32_t ar  = (uint32_t)((lane & 7) + ((lane >> 3) & 1) * 8);
    uint32_t akb = (uint32_t)(((lane >> 4) & 1) * 16);
    uint32_t br  = (uint32_t)((lane & 7) + ((lane >> 4) & 1) * 8);
    uint32_t bkb = (uint32_t)(((lane >> 3) & 1) * 16);

    float acc[2][8][4];
    #pragma unroll
    for (int i = 0; i < 2; i++)
        #pragma unroll
        for (int j = 0; j < 8; j++)
            #pragma unroll
            for (int q = 0; q < 4; q++) acc[i][j][q] = 0.0f;

    F_ISSUE(0, 0);
    F_ISSUE(1, 1);

    for (int c = 0; c < NCHUNK; c++) {
        if (c < NCHUNK - 1) { CP_WAIT(1); } else { CP_WAIT(0); }
        __syncthreads();
        if (c + 2 < NCHUNK) F_ISSUE((c + 2) % NSTAGE, c + 2);

        uint32_t sb = tbase + (uint32_t)(c % NSTAGE) * F_STAGE;
        uint32_t tAf = sb;
        uint32_t tBf = sb + F_TILE_A;

        #pragma unroll
        for (int k16 = 0; k16 < 4; k16++) {
            uint32_t kb = (uint32_t)k16 * 32u;
            uint32_t af[2][4], bf[4][4];
            #pragma unroll
            for (int mt = 0; mt < 2; mt++)
                ldsm4(swaddr(tAf, (uint32_t)(warp_m * 32 + mt * 16) + ar, kb + akb), af[mt]);
            #pragma unroll
            for (int p = 0; p < 4; p++)
                ldsm4(swaddr(tBf, (uint32_t)(warp_n * 64 + p * 16) + br, kb + bkb), bf[p]);
            #pragma unroll
            for (int mt = 0; mt < 2; mt++)
                #pragma unroll
                for (int p = 0; p < 4; p++) {
                    mma16816h(acc[mt][2 * p],     af[mt], &bf[p][0]);
                    mma16816h(acc[mt][2 * p + 1], af[mt], &bf[p][2]);
                }
        }
    }

    // ---- epilogue ----
    float* Co = C;
    const float* bp = bias;
    __half* So = Sf;
    if (n0 >= 1024) { Co = C2; bp = bias2; So = Sf2; }
    int nbase = n0 & 1023;
    int lm = lane >> 2;
    int lc = (lane & 3) * 2;
    int cm = m0 + warp_m * 32;
    int cn = nbase + warp_n * 64;
    #pragma unroll
    for (int mt = 0; mt < 2; mt++) {
        #pragma unroll
        for (int nt = 0; nt < 8; nt++) {
            int r0 = cm + mt * 16 + lm;
            int cc = cn + nt * 8 + lc;
            float2 bv = *(const float2*)&bp[cc];
            float* a = acc[mt][nt];
            float2 o0 = make_float2(a[0] + bv.x, a[1] + bv.y);
            float2 o1 = make_float2(a[2] + bv.x, a[3] + bv.y);
            size_t off0 = (size_t)r0 * DDIM + cc;
            size_t off1 = (size_t)(r0 + 8) * DDIM + cc;
            if (doAdd) {
                float2 q0 = *(const float2*)(addp + off0);
                float2 q1 = *(const float2*)(addp + off1);
                o0.x += q0.x; o0.y += q0.y;
                o1.x += q1.x; o1.y += q1.y;
            }
            if (Co) {
                *(float2*)(Co + off0) = o0;
                *(float2*)(Co + off1) = o1;
            }
            if (So) {
                *(__half2*)(So + off0) = __floats2half2_rn(o0.x, o0.y);
                *(__half2*)(So + off1) = __floats2half2_rn(o1.x, o1.y);
            }
        }
    }
}

// ---------------- rmsnorm -> fp16 ------------------------------------------
__global__ void rmsnorm_f16_kernel(const float* __restrict__ x,
                                   const float* __restrict__ gw,
                                   __half* __restrict__ Sf) {
    int row = blockIdx.x;
    const float4* xr = (const float4*)(x + (size_t)row * DDIM);
    float4 v = xr[threadIdx.x];
    float ss = v.x * v.x + v.y * v.y + v.z * v.z + v.w * v.w;
    #pragma unroll
    for (int o = 16; o > 0; o >>= 1) ss += __shfl_xor_sync(0xffffffffu, ss, o);
    __shared__ float sred[8];
    if ((threadIdx.x & 31) == 0) sred[threadIdx.x >> 5] = ss;
    __syncthreads();
    float total = 0.0f;
    #pragma unroll
    for (int i = 0; i < 8; i++) total += sred[i];
    float n = fmaxf(sqrtf(total), 1e-12f);
    float s = 32.0f / n;
    float4 g = ((const float4*)gw)[threadIdx.x];
    float o0 = v.x * s * g.x, o1 = v.y * s * g.y;
    float o2 = v.z * s * g.z, o3 = v.w * s * g.w;
    size_t base2 = (size_t)row * (DDIM / 2) + threadIdx.x * 2;
    ((__half2*)Sf)[base2]     = __floats2half2_rn(o0, o1);
    ((__half2*)Sf)[base2 + 1] = __floats2half2_rn(o2, o3);
}

// ---------------- chunked RG-LRU scan (half2, 2 chains/thread) -------------
// pass 1: fused gate computation + per-chunk local scan
__global__ void scan1_kernel(const __half* __restrict__ rt, const __half* __restrict__ it,
                             const __half* __restrict__ rg, const float* __restrict__ Lam,
                             __half* __restrict__ hl,
                             float* __restrict__ Acar, float* __restrict__ Hcar) {
    int i = blockIdx.x * 256 + threadIdx.x;     // 0 .. 65535 (chain-pairs x chunks)
    int cp = i & (NCHAIN / 2 - 1);              // chain-pair 0..2047
    int chunk = i >> 11;
    int b = cp >> 9;
    int dp = cp & 511;                          // d = 2*dp
    size_t base2 = (((size_t)b * TLEN + (size_t)chunk * CHLEN) * DDIM) / 2 + dp;
    float2 lam = *(const float2*)&Lam[2 * dp];
    float la0 = -log1pf(expf(-lam.x));
    float la1 = -log1pf(expf(-lam.y));
    float h0 = 0.0f, h1 = 0.0f, P0 = 1.0f, P1 = 1.0f;
    const __half2* rt2 = (const __half2*)rt;
    const __half2* it2 = (const __half2*)it;
    const __half2* rg2 = (const __half2*)rg;
    __half2* hl2 = (__half2*)hl;
    for (int t = 0; t < CHLEN; t++) {
        size_t a_ = base2 + (size_t)t * (DDIM / 2);
        __half2 rv = rt2[a_], iv = it2[a_], xv = rg2[a_];
        float a0 = expf(la0 * sigmoidf_(__low2float(rv)) * 0.125f);
        float a1 = expf(la1 * sigmoidf_(__high2float(rv)) * 0.125f);
        float gg0 = sqrtf(fmaxf(1.0f - a0 * a0, 0.0f)) * sigmoidf_(__low2float(iv)) * __low2float(xv);
        float gg1 = sqrtf(fmaxf(1.0f - a1 * a1, 0.0f)) * sigmoidf_(__high2float(iv)) * __high2float(xv);
        h0 = fmaf(a0, h0, gg0);
        h1 = fmaf(a1, h1, gg1);
        P0 *= a0; P1 *= a1;
        hl2[a_] = __floats2half2_rn(h0, h1);
    }
    int chain = b * DDIM + 2 * dp;
    Acar[chunk * NCHAIN + chain]     = P0;
    Acar[chunk * NCHAIN + chain + 1] = P1;
    Hcar[chunk * NCHAIN + chain]     = h0;
    Hcar[chunk * NCHAIN + chain + 1] = h1;
}

// pass 2: serial scan over chunk aggregates (per chain)
__global__ void scan2_kernel(const float* __restrict__ Acar, const float* __restrict__ Hcar,
                             float* __restrict__ carry) {
    int chain = blockIdx.x * 256 + threadIdx.x;   // 0..4095
    float h = 0.0f;
    #pragma unroll
    for (int c = 0; c < CHUNKS; c++) {
        int idx = c * NCHAIN + chain;
        carry[idx] = h;
        h = fmaf(Acar[idx], h, Hcar[idx]);
    }
}

// pass 3: apply carry, fused gelu(lin)*h, fp16 in-place on lin buffer
__global__ void scan3_kernel(const __half* __restrict__ rt, const __half* __restrict__ hl,
                             const float* __restrict__ carry,
                             const float* __restrict__ Lam,
                             __half* __restrict__ linSf) {
    int i = blockIdx.x * 256 + threadIdx.x;     // 0 .. 65535
    int cp = i & (NCHAIN / 2 - 1);
    int chunk = i >> 11;
    int b = cp >> 9;
    int dp = cp & 511;
    size_t base2 = (((size_t)b * TLEN + (size_t)chunk * CHLEN) * DDIM) / 2 + dp;
    float2 lam = *(const float2*)&Lam[2 * dp];
    float la0 = -log1pf(expf(-lam.x));
    float la1 = -log1pf(expf(-lam.y));
    int chain = b * DDIM + 2 * dp;
    float cin0 = carry[chunk * NCHAIN + chain];
    float cin1 = carry[chunk * NCHAIN + chain + 1];
    float P0 = 1.0f, P1 = 1.0f;
    const __half2* rt2 = (const __half2*)rt;
    const __half2* hl2 = (const __half2*)hl;
    __half2* ls2 = (__half2*)linSf;
    for (int t = 0; t < CHLEN; t++) {
        size_t a_ = base2 + (size_t)t * (DDIM / 2);
        __half2 rv = rt2[a_];
        __half2 hv = hl2[a_];
        __half2 lv = ls2[a_];
        float a0 = expf(la0 * sigmoidf_(__low2float(rv)) * 0.125f);
        float a1 = expf(la1 * sigmoidf_(__high2float(rv)) * 0.125f);
        P0 *= a0; P1 *= a1;
        float h0 = fmaf(P0, cin0, __low2float(hv));
        float h1 = fmaf(P1, cin1, __high2float(hv));
        float o0 = gelu_exact(__low2float(lv)) * h0;
        float o1 = gelu_exact(__high2float(lv)) * h1;
        ls2[a_] = __floats2half2_rn(o0, o1);
    }
}

// ---------------- gelu(sigmoid(t1)) * t2 -> fp16 ---------------------------
__global__ void comb_f16_kernel(const __half* __restrict__ t1,
                                const __half* __restrict__ t2,
                                __half* __restrict__ Sf) {
    int i = blockIdx.x * blockDim.x + threadIdx.x;
    if (i >= MROWS * DDIM / 2) return;
    __half2 a2 = ((const __half2*)t1)[i];
    __half2 b2 = ((const __half2*)t2)[i];
    float a0 = __low2float(a2), a1 = __high2float(a2);
    float b0 = __low2float(b2), b1 = __high2float(b2);
    float o0 = gelu_exact(sigmoidf_(a0)) * b0;
    float o1 = gelu_exact(sigmoidf_(a1)) * b1;
    ((__half2*)Sf)[i] = __floats2half2_rn(o0, o1);
}

// ---------------- launch ---------------------------------------------------
extern "C" void kernel_launch(void* const* d_in, const int* in_sizes, int n_in,
                              void* d_out, int out_size) {
    const float* x      = (const float*)d_in[0];
    const float* g1     = (const float*)d_in[1];
    const float* g2     = (const float*)d_in[2];
    const float* W_lin  = (const float*)d_in[3];
    const float* b_lin  = (const float*)d_in[4];
    const float* W_conv = (const float*)d_in[5];
    const float* b_conv = (const float*)d_in[6];
    const float* W_lin2 = (const float*)d_in[7];
    const float* b_lin2 = (const float*)d_in[8];
    const float* Wa     = (const float*)d_in[9];
    const float* ba     = (const float*)d_in[10];
    const float* Wx     = (const float*)d_in[11];
    const float* bx     = (const float*)d_in[12];
    const float* Lam    = (const float*)d_in[13];
    const float* W1     = (const float*)d_in[14];
    const float* b1     = (const float*)d_in[15];
    const float* W2     = (const float*)d_in[16];
    const float* b2     = (const float*)d_in[17];
    const float* W3     = (const float*)d_in[18];
    const float* b3     = (const float*)d_in[19];
    float* out = (float*)d_out;

    float *res, *Acar, *Hcar, *carry;
    __half *hl, *Af, *Af2, *rt16, *it16, *Wf;
    cudaGetSymbolAddress((void**)&res, g_res);
    cudaGetSymbolAddress((void**)&hl,  g_hl);
    cudaGetSymbolAddress((void**)&Acar, g_Acar);
    cudaGetSymbolAddress((void**)&Hcar, g_Hcar);
    cudaGetSymbolAddress((void**)&carry, g_carry);
    cudaGetSymbolAddress((void**)&Af,   g_Af);
    cudaGetSymbolAddress((void**)&Af2,  g_Af2);
    cudaGetSymbolAddress((void**)&rt16, g_rt16);
    cudaGetSymbolAddress((void**)&it16, g_it16);
    cudaGetSymbolAddress((void**)&Wf,   g_Wf);

    const int FGEMM_SMEM = NSTAGE * F_STAGE + 1024;   // 99328
    cudaFuncSetAttribute(fgemm_kernel,
                         cudaFuncAttributeMaxDynamicSharedMemorySize, FGEMM_SMEM);

    dim3 gg1(DDIM / 128, MROWS / 128);       // (8, 128)   N=1024
    dim3 gg2(2 * DDIM / 128, MROWS / 128);   // (16, 128)  N=2048
    dim3 cw(DDIM * DDIM / 4 / 256, 8);       // (1024, 8)  all weights
    int ewBlocks  = (MROWS * DDIM / 2 + 255) / 256;
    int scBlocks  = (NCHAIN / 2 * CHUNKS) / 256;   // 256
    const size_t WN = (size_t)DDIM * DDIM;

    const float* FZ = (const float*)nullptr;
    float* FZo = (float*)nullptr;
    __half* HZ = (__half*)nullptr;

    // 0) convert all 8 weights to fp16 slots:
    //    0:W_lin 1:W_conv 2:Wa 3:Wx 4:W_lin2 5:W1 6:W2 7:W3
    conv_all_w_kernel<<<cw, 256>>>(W_lin, W_conv, Wa, Wx, W_lin2, W1, W2, W3, Wf);
    // 1) Af = fp16(rmsnorm(x, g1))
    rmsnorm_f16_kernel<<<MROWS, 256>>>(x, g1, Af);
    // 2) lin(fp16 Af2) = xn @ W_lin^T + b_lin
    fgemm_kernel<<<gg1, 256, FGEMM_SMEM>>>(Af, Wf, b_lin, FZ, FZo, 0, Af2, FZ, FZo, HZ);
    // 3) rg(fp16 Af) = lin @ W_conv^T + b_conv
    fgemm_kernel<<<gg1, 256, FGEMM_SMEM>>>(Af2, Wf + WN, b_conv, FZ, FZo, 0, Af, FZ, FZo, HZ);
    // 4) merged: rt16 = rg @ Wa^T + ba ; it16 = rg @ Wx^T + bx  (slots 2,3)
    fgemm_kernel<<<gg2, 256, FGEMM_SMEM>>>(Af, Wf + 2 * WN, ba, FZ, FZo, 0, rt16, bx, FZo, it16);
    // 5-7) chunked scan: gateprep + local scan, aggregate scan, carry + gelu*h
    scan1_kernel<<<scBlocks, 256>>>(rt16, it16, Af, Lam, hl, Acar, Hcar);
    scan2_kernel<<<NCHAIN / 256, 256>>>(Acar, Hcar, carry);
    scan3_kernel<<<scBlocks, 256>>>(rt16, hl, carry, Lam, Af2);
    // 8) res = (gelu(lin)*h) @ W_lin2^T + b_lin2 + x   (slot 4)
    fgemm_kernel<<<gg1, 256, FGEMM_SMEM>>>(Af2, Wf + 4 * WN, b_lin2, x, res, 1, HZ, FZ, FZo, HZ);
    // 9) Af = fp16(rmsnorm(res, g2))
    rmsnorm_f16_kernel<<<MROWS, 256>>>(res, g2, Af);
    // 10) merged: rt16 = xm @ W1^T + b1 ; it16 = xm @ W2^T + b2  (slots 5,6)
    fgemm_kernel<<<gg2, 256, FGEMM_SMEM>>>(Af, Wf + 5 * WN, b1, FZ, FZo, 0, rt16, b2, FZo, it16);
    // 11) Af2 = fp16(gelu(sigmoid(rt)) * it)
    comb_f16_kernel<<<ewBlocks, 256>>>(rt16, it16, Af2);
    // 12) out = combined @ W3^T + b3 + res   (slot 7)
    fgemm_kernel<<<gg1, 256, FGEMM_SMEM>>>(Af2, Wf + 7 * WN, b3, res, out, 1, HZ, FZ, FZo, HZ);

    (void)in_sizes; (void)n_in; (void)out_size;
}

// round 13
// speedup vs baseline: 1.0829x; 1.0829x over previous
#include <cuda_runtime.h>
#include <cuda_fp16.h>
#include <math.h>
#include <cstdint>

// Problem dims
#define MROWS 16384   // B*T = 4*4096
#define DDIM  1024
#define TLEN  4096
#define CHUNKS 64
#define CHLEN  (TLEN / CHUNKS)   // 64
#define NCHAIN 4096              // B * D

// ---------------- scratch (device globals; no allocation allowed) ----------
__device__ float g_res[MROWS * DDIM];
__device__ __half g_hl [MROWS * DDIM];
__device__ __half g_Af  [MROWS * DDIM];
__device__ __half g_Af2 [MROWS * DDIM];
__device__ __half g_rt16[MROWS * DDIM];
__device__ __half g_it16[MROWS * DDIM];
__device__ __half g_Wf [8 * DDIM * DDIM];   // 8 weight slots
__device__ float g_Acar[NCHAIN * CHUNKS];
__device__ float g_Hcar[NCHAIN * CHUNKS];
__device__ float g_carry[NCHAIN * CHUNKS];

// ---------------- base-ISA tensor helpers ----------------------------------
__device__ __forceinline__ uint32_t smem_to_u32(const void* p) {
    uint32_t a;
    asm("{ .reg .u64 t; cvta.to.shared.u64 t, %1; cvt.u32.u64 %0, t; }"
        : "=r"(a) : "l"(p));
    return a;
}
__device__ __forceinline__ void cpasync16(uint32_t dst, const void* src) {
    asm volatile("cp.async.cg.shared.global [%0], [%1], 16;"
                 :: "r"(dst), "l"(src) : "memory");
}
#define CP_COMMIT() asm volatile("cp.async.commit_group;" ::: "memory")
#define CP_WAIT(n)  asm volatile("cp.async.wait_group %0;" :: "n"(n) : "memory")

__device__ __forceinline__ void ldsm4(uint32_t addr, uint32_t* r) {
    asm volatile("ldmatrix.sync.aligned.m8n8.x4.shared.b16 {%0,%1,%2,%3}, [%4];"
                 : "=r"(r[0]), "=r"(r[1]), "=r"(r[2]), "=r"(r[3]) : "r"(addr));
}
__device__ __forceinline__ void mma16816h(float* c, const uint32_t* a, const uint32_t* b) {
    asm volatile(
        "mma.sync.aligned.m16n8k16.row.col.f32.f16.f16.f32 "
        "{%0,%1,%2,%3}, {%4,%5,%6,%7}, {%8,%9}, {%0,%1,%2,%3};"
        : "+f"(c[0]), "+f"(c[1]), "+f"(c[2]), "+f"(c[3])
        : "r"(a[0]), "r"(a[1]), "r"(a[2]), "r"(a[3]), "r"(b[0]), "r"(b[1]));
}

// ---------------- math helpers ---------------------------------------------
__device__ __forceinline__ float gelu_exact(float x) {
    return 0.5f * x * (1.0f + erff(x * 0.70710678118654752440f));
}
__device__ __forceinline__ float sigmoidf_(float x) {
    return 1.0f / (1.0f + expf(-x));
}
__device__ __forceinline__ float h2lo(uint32_t u) {
    __half2 h = *(__half2*)&u;
    return __low2float(h);
}
__device__ __forceinline__ float h2hi(uint32_t u) {
    __half2 h = *(__half2*)&u;
    return __high2float(h);
}
__device__ __forceinline__ uint32_t pack2h(float a, float b) {
    __half2 h = __floats2half2_rn(a, b);
    return *(uint32_t*)&h;
}

// ---------------- fp32 -> fp16 convert: all 8 weights, MLP=2 ---------------
__global__ void conv_all_w_kernel(const float* __restrict__ w0, const float* __restrict__ w1,
                                  const float* __restrict__ w2, const float* __restrict__ w3,
                                  const float* __restrict__ w4, const float* __restrict__ w5,
                                  const float* __restrict__ w6, const float* __restrict__ w7,
                                  __half* __restrict__ dst) {
    const float* srcs[8] = {w0, w1, w2, w3, w4, w5, w6, w7};
    int slot = blockIdx.y;
    const float* src = srcs[slot];
    __half* d = dst + (size_t)slot * DDIM * DDIM;
    int i = (blockIdx.x * 256 + threadIdx.x) * 2;     // 2 float4 per thread
    float4 v0 = ((const float4*)src)[i];
    float4 v1 = ((const float4*)src)[i + 1];
    ((__half2*)d)[2 * i]     = __floats2half2_rn(v0.x, v0.y);
    ((__half2*)d)[2 * i + 1] = __floats2half2_rn(v0.z, v0.w);
    ((__half2*)d)[2 * i + 2] = __floats2half2_rn(v1.x, v1.y);
    ((__half2*)d)[2 * i + 3] = __floats2half2_rn(v1.z, v1.w);
}

// ---------------- fp16 1-term mma.sync GEMM, BN=128, 2-stage ---------------
#define F_TILE_A 16384               // 128 x 64 fp16
#define F_TILE_B 16384               // 128 x 64 fp16
#define F_STAGE  32768
#define NCHUNK (DDIM / 64)           // 16

__device__ __forceinline__ uint32_t swaddr(uint32_t tile, uint32_t row, uint32_t kb) {
    uint32_t off = row * 128u + kb;
    return tile + (off ^ ((off >> 3) & 0x70u));
}

__global__ void __launch_bounds__(256, 2)
fgemm_kernel(const __half* __restrict__ Af, const __half* __restrict__ Bf,
             const float* __restrict__ bias, const float* __restrict__ addp,
             float* __restrict__ C, int doAdd,
             __half* __restrict__ Sf,
             const float* __restrict__ bias2, float* __restrict__ C2,
             __half* __restrict__ Sf2) {
    extern __shared__ __align__(1024) char smem_raw[];
    uint32_t smem0 = smem_to_u32(smem_raw);
    uint32_t tbase = (smem0 + 1023u) & ~1023u;

    int tid = threadIdx.x;
    int wid = tid >> 5;
    int lane = tid & 31;
    int m0 = blockIdx.y * 128;
    int n0 = blockIdx.x * 128;

    int row_base = tid >> 3;        // 0..31
    int col = tid & 7;
    const char* srcb[8];
    uint32_t stsoff[8];
    {
        const char* aB = (const char*)(Af + (size_t)m0 * DDIM);
        const char* bB = (const char*)(Bf + (size_t)n0 * DDIM);
        #pragma unroll
        for (int i = 0; i < 4; i++) {
            uint32_t rr = (uint32_t)row_base + 32u * i;
            srcb[i] = aB + (size_t)rr * 2048 + col * 16;
            uint32_t off = rr * 128u + (uint32_t)col * 16u;
            stsoff[i] = off ^ ((off >> 3) & 0x70u);
        }
        #pragma unroll
        for (int i = 4; i < 8; i++) {
            uint32_t rr = (uint32_t)row_base + 32u * (i - 4);
            srcb[i] = bB + (size_t)rr * 2048 + col * 16;
            uint32_t off = rr * 128u + (uint32_t)col * 16u;
            stsoff[i] = F_TILE_A + (off ^ ((off >> 3) & 0x70u));
        }
    }

    #define F_ISSUE(buf, chunk) do { \
        uint32_t db_ = tbase + (uint32_t)(buf) * F_STAGE; \
        _Pragma("unroll") \
        for (int i_ = 0; i_ < 8; i_++) \
            cpasync16(db_ + stsoff[i_], srcb[i_] + (size_t)(chunk) * 128); \
        CP_COMMIT(); \
    } while (0)

    int warp_m = wid & 3;
    int warp_n = wid >> 2;          // 0..1
    uint32_t ar  = (uint32_t)((lane & 7) + ((lane >> 3) & 1) * 8);
    uint32_t akb = (uint32_t)(((lane >> 4) & 1) * 16);
    uint32_t br  = (uint32_t)((lane & 7) + ((lane >> 4) & 1) * 8);
    uint32_t bkb = (uint32_t)(((lane >> 3) & 1) * 16);

    float acc[2][8][4];
    #pragma unroll
    for (int i = 0; i < 2; i++)
        #pragma unroll
        for (int j = 0; j < 8; j++)
            #pragma unroll
            for (int q = 0; q < 4; q++) acc[i][j][q] = 0.0f;

    F_ISSUE(0, 0);

    for (int c = 0; c < NCHUNK; c++) {
        CP_WAIT(0);
        __syncthreads();
        if (c + 1 < NCHUNK) F_ISSUE((c + 1) & 1, c + 1);

        uint32_t sb = tbase + (uint32_t)(c & 1) * F_STAGE;
        uint32_t tAf = sb;
        uint32_t tBf = sb + F_TILE_A;

        #pragma unroll
        for (int k16 = 0; k16 < 4; k16++) {
            uint32_t kb = (uint32_t)k16 * 32u;
            uint32_t af[2][4], bf[4][4];
            #pragma unroll
            for (int mt = 0; mt < 2; mt++)
                ldsm4(swaddr(tAf, (uint32_t)(warp_m * 32 + mt * 16) + ar, kb + akb), af[mt]);
            #pragma unroll
            for (int p = 0; p < 4; p++)
                ldsm4(swaddr(tBf, (uint32_t)(warp_n * 64 + p * 16) + br, kb + bkb), bf[p]);
            #pragma unroll
            for (int mt = 0; mt < 2; mt++)
                #pragma unroll
                for (int p = 0; p < 4; p++) {
                    mma16816h(acc[mt][2 * p],     af[mt], &bf[p][0]);
                    mma16816h(acc[mt][2 * p + 1], af[mt], &bf[p][2]);
                }
        }
    }

    float* Co = C;
    const float* bp = bias;
    __half* So = Sf;
    if (n0 >= 1024) { Co = C2; bp = bias2; So = Sf2; }
    int nbase = n0 & 1023;
    int lm = lane >> 2;
    int lc = (lane & 3) * 2;
    int cm = m0 + warp_m * 32;
    int cn = nbase + warp_n * 64;
    #pragma unroll
    for (int mt = 0; mt < 2; mt++) {
        #pragma unroll
        for (int nt = 0; nt < 8; nt++) {
            int r0 = cm + mt * 16 + lm;
            int cc = cn + nt * 8 + lc;
            float2 bv = *(const float2*)&bp[cc];
            float* a = acc[mt][nt];
            float2 o0 = make_float2(a[0] + bv.x, a[1] + bv.y);
            float2 o1 = make_float2(a[2] + bv.x, a[3] + bv.y);
            size_t off0 = (size_t)r0 * DDIM + cc;
            size_t off1 = (size_t)(r0 + 8) * DDIM + cc;
            if (doAdd) {
                float2 q0 = *(const float2*)(addp + off0);
                float2 q1 = *(const float2*)(addp + off1);
                o0.x += q0.x; o0.y += q0.y;
                o1.x += q1.x; o1.y += q1.y;
            }
            if (Co) {
                *(float2*)(Co + off0) = o0;
                *(float2*)(Co + off1) = o1;
            }
            if (So) {
                *(__half2*)(So + off0) = __floats2half2_rn(o0.x, o0.y);
                *(__half2*)(So + off1) = __floats2half2_rn(o1.x, o1.y);
            }
        }
    }
}

// ---------------- rmsnorm -> fp16, 4 rows per block (MLP=4) ----------------
__global__ void rmsnorm_f16_kernel(const float* __restrict__ x,
                                   const float* __restrict__ gw,
                                   __half* __restrict__ Sf) {
    int row0 = blockIdx.x * 4;
    int tid = threadIdx.x;
    float4 v[4];
    #pragma unroll
    for (int j = 0; j < 4; j++)
        v[j] = ((const float4*)(x + (size_t)(row0 + j) * DDIM))[tid];
    float4 g = ((const float4*)gw)[tid];

    float ps[4];
    #pragma unroll
    for (int j = 0; j < 4; j++)
        ps[j] = v[j].x * v[j].x + v[j].y * v[j].y + v[j].z * v[j].z + v[j].w * v[j].w;
    #pragma unroll
    for (int j = 0; j < 4; j++)
        #pragma unroll
        for (int o = 16; o > 0; o >>= 1)
            ps[j] += __shfl_xor_sync(0xffffffffu, ps[j], o);

    __shared__ float sred[4][8];
    if ((tid & 31) == 0)
        #pragma unroll
        for (int j = 0; j < 4; j++) sred[j][tid >> 5] = ps[j];
    __syncthreads();
    float s[4];
    #pragma unroll
    for (int j = 0; j < 4; j++) {
        float total = 0.0f;
        #pragma unroll
        for (int i = 0; i < 8; i++) total += sred[j][i];
        s[j] = 32.0f / fmaxf(sqrtf(total), 1e-12f);
    }
    #pragma unroll
    for (int j = 0; j < 4; j++) {
        float o0 = v[j].x * s[j] * g.x, o1 = v[j].y * s[j] * g.y;
        float o2 = v[j].z * s[j] * g.z, o3 = v[j].w * s[j] * g.w;
        size_t base2 = (size_t)(row0 + j) * (DDIM / 2) + tid * 2;
        ((__half2*)Sf)[base2]     = __floats2half2_rn(o0, o1);
        ((__half2*)Sf)[base2 + 1] = __floats2half2_rn(o2, o3);
    }
}

// ---------------- chunked RG-LRU scan (4 chains/thread, uint2) -------------
// pass 1: fused gate computation + per-chunk local scan
__global__ void scan1_kernel(const __half* __restrict__ rt, const __half* __restrict__ it,
                             const __half* __restrict__ rg, const float* __restrict__ Lam,
                             __half* __restrict__ hl,
                             float* __restrict__ Acar, float* __restrict__ Hcar) {
    int i = blockIdx.x * 256 + threadIdx.x;     // 0 .. 65535 (quads x chunks)
    int q = i & 1023;                           // chain-quad within batch grid
    int chunk = i >> 10;
    int b = q >> 8;
    int dq = q & 255;                           // d = 4*dq
    size_t base4 = (((size_t)b * TLEN + (size_t)chunk * CHLEN) * DDIM) / 4 + dq;
    float la[4];
    {
        float4 lam = *(const float4*)&Lam[4 * dq];
        la[0] = -log1pf(expf(-lam.x)); la[1] = -log1pf(expf(-lam.y));
        la[2] = -log1pf(expf(-lam.z)); la[3] = -log1pf(expf(-lam.w));
    }
    float h[4] = {0, 0, 0, 0}, P[4] = {1, 1, 1, 1};
    const uint2* rt4 = (const uint2*)rt;
    const uint2* it4 = (const uint2*)it;
    const uint2* rg4 = (const uint2*)rg;
    uint2* hl4 = (uint2*)hl;
    #pragma unroll 4
    for (int t = 0; t < CHLEN; t++) {
        size_t a_ = base4 + (size_t)t * (DDIM / 4);
        uint2 rv = rt4[a_], iv = it4[a_], xv = rg4[a_];
        float rr[4] = {h2lo(rv.x), h2hi(rv.x), h2lo(rv.y), h2hi(rv.y)};
        float ii[4] = {h2lo(iv.x), h2hi(iv.x), h2lo(iv.y), h2hi(iv.y)};
        float xx[4] = {h2lo(xv.x), h2hi(xv.x), h2lo(xv.y), h2hi(xv.y)};
        float hh[4];
        #pragma unroll
        for (int j = 0; j < 4; j++) {
            float a = expf(la[j] * sigmoidf_(rr[j]) * 0.125f);
            float gg = sqrtf(fmaxf(1.0f - a * a, 0.0f)) * sigmoidf_(ii[j]) * xx[j];
            h[j] = fmaf(a, h[j], gg);
            P[j] *= a;
            hh[j] = h[j];
        }
        uint2 ho;
        ho.x = pack2h(hh[0], hh[1]);
        ho.y = pack2h(hh[2], hh[3]);
        hl4[a_] = ho;
    }
    int chain = b * DDIM + 4 * dq;
    #pragma unroll
    for (int j = 0; j < 4; j++) {
        Acar[chunk * NCHAIN + chain + j] = P[j];
        Hcar[chunk * NCHAIN + chain + j] = h[j];
    }
}

// pass 2: serial scan over chunk aggregates (per chain)
__global__ void scan2_kernel(const float* __restrict__ Acar, const float* __restrict__ Hcar,
                             float* __restrict__ carry) {
    int chain = blockIdx.x * 256 + threadIdx.x;   // 0..4095
    float h = 0.0f;
    #pragma unroll
    for (int c = 0; c < CHUNKS; c++) {
        int idx = c * NCHAIN + chain;
        carry[idx] = h;
        h = fmaf(Acar[idx], h, Hcar[idx]);
    }
}

// pass 3: apply carry, fused gelu(lin)*h, fp16 in-place on lin buffer
__global__ void scan3_kernel(const __half* __restrict__ rt, const __half* __restrict__ hl,
                             const float* __restrict__ carry,
                             const float* __restrict__ Lam,
                             __half* __restrict__ linSf) {
    int i = blockIdx.x * 256 + threadIdx.x;     // 0 .. 65535
    int q = i & 1023;
    int chunk = i >> 10;
    int b = q >> 8;
    int dq = q & 255;
    size_t base4 = (((size_t)b * TLEN + (size_t)chunk * CHLEN) * DDIM) / 4 + dq;
    float la[4];
    {
        float4 lam = *(const float4*)&Lam[4 * dq];
        la[0] = -log1pf(expf(-lam.x)); la[1] = -log1pf(expf(-lam.y));
        la[2] = -log1pf(expf(-lam.z)); la[3] = -log1pf(expf(-lam.w));
    }
    int chain = b * DDIM + 4 * dq;
    float cin[4], P[4] = {1, 1, 1, 1};
    #pragma unroll
    for (int j = 0; j < 4; j++) cin[j] = carry[chunk * NCHAIN + chain + j];
    const uint2* rt4 = (const uint2*)rt;
    const uint2* hl4 = (const uint2*)hl;
    uint2* ls4 = (uint2*)linSf;
    #pragma unroll 4
    for (int t = 0; t < CHLEN; t++) {
        size_t a_ = base4 + (size_t)t * (DDIM / 4);
        uint2 rv = rt4[a_], hv = hl4[a_], lv = ls4[a_];
        float rr[4] = {h2lo(rv.x), h2hi(rv.x), h2lo(rv.y), h2hi(rv.y)};
        float hh[4] = {h2lo(hv.x), h2hi(hv.x), h2lo(hv.y), h2hi(hv.y)};
        float ll[4] = {h2lo(lv.x), h2hi(lv.x), h2lo(lv.y), h2hi(lv.y)};
        float oo[4];
        #pragma unroll
        for (int j = 0; j < 4; j++) {
            float a = expf(la[j] * sigmoidf_(rr[j]) * 0.125f);
            P[j] *= a;
            float h = fmaf(P[j], cin[j], hh[j]);
            oo[j] = gelu_exact(ll[j]) * h;
        }
        uint2 o;
        o.x = pack2h(oo[0], oo[1]);
        o.y = pack2h(oo[2], oo[3]);
        ls4[a_] = o;
    }
}

// ---------------- gelu(sigmoid(t1)) * t2 -> fp16 (uint4, MLP=2) ------------
__global__ void comb_f16_kernel(const __half* __restrict__ t1,
                                const __half* __restrict__ t2,
                                __half* __restrict__ Sf) {
    int i = blockIdx.x * blockDim.x + threadIdx.x;    // uint4 index (8 halves)
    if (i >= MROWS * DDIM / 8) return;
    uint4 a4 = ((const uint4*)t1)[i];
    uint4 b4 = ((const uint4*)t2)[i];
    uint32_t av[4] = {a4.x, a4.y, a4.z, a4.w};
    uint32_t bv[4] = {b4.x, b4.y, b4.z, b4.w};
    uint32_t ov[4];
    #pragma unroll
    for (int j = 0; j < 4; j++) {
        float a0 = h2lo(av[j]), a1 = h2hi(av[j]);
        float b0 = h2lo(bv[j]), b1 = h2hi(bv[j]);
        float o0 = gelu_exact(sigmoidf_(a0)) * b0;
        float o1 = gelu_exact(sigmoidf_(a1)) * b1;
        ov[j] = pack2h(o0, o1);
    }
    uint4 o4 = make_uint4(ov[0], ov[1], ov[2], ov[3]);
    ((uint4*)Sf)[i] = o4;
}

// ---------------- launch ---------------------------------------------------
extern "C" void kernel_launch(void* const* d_in, const int* in_sizes, int n_in,
                              void* d_out, int out_size) {
    const float* x      = (const float*)d_in[0];
    const float* g1     = (const float*)d_in[1];
    const float* g2     = (const float*)d_in[2];
    const float* W_lin  = (const float*)d_in[3];
    const float* b_lin  = (const float*)d_in[4];
    const float* W_conv = (const float*)d_in[5];
    const float* b_conv = (const float*)d_in[6];
    const float* W_lin2 = (const float*)d_in[7];
    const float* b_lin2 = (const float*)d_in[8];
    const float* Wa     = (const float*)d_in[9];
    const float* ba     = (const float*)d_in[10];
    const float* Wx     = (const float*)d_in[11];
    const float* bx     = (const float*)d_in[12];
    const float* Lam    = (const float*)d_in[13];
    const float* W1     = (const float*)d_in[14];
    const float* b1     = (const float*)d_in[15];
    const float* W2     = (const float*)d_in[16];
    const float* b2     = (const float*)d_in[17];
    const float* W3     = (const float*)d_in[18];
    const float* b3     = (const float*)d_in[19];
    float* out = (float*)d_out;

    float *res, *Acar, *Hcar, *carry;
    __half *hl, *Af, *Af2, *rt16, *it16, *Wf;
    cudaGetSymbolAddress((void**)&res, g_res);
    cudaGetSymbolAddress((void**)&hl,  g_hl);
    cudaGetSymbolAddress((void**)&Acar, g_Acar);
    cudaGetSymbolAddress((void**)&Hcar, g_Hcar);
    cudaGetSymbolAddress((void**)&carry, g_carry);
    cudaGetSymbolAddress((void**)&Af,   g_Af);
    cudaGetSymbolAddress((void**)&Af2,  g_Af2);
    cudaGetSymbolAddress((void**)&rt16, g_rt16);
    cudaGetSymbolAddress((void**)&it16, g_it16);
    cudaGetSymbolAddress((void**)&Wf,   g_Wf);

    const int FGEMM_SMEM = 2 * F_STAGE + 1024;   // 66560
    cudaFuncSetAttribute(fgemm_kernel,
                         cudaFuncAttributeMaxDynamicSharedMemorySize, FGEMM_SMEM);

    dim3 gg1(DDIM / 128, MROWS / 128);       // (8, 128)   N=1024
    dim3 gg2(2 * DDIM / 128, MROWS / 128);   // (16, 128)  N=2048
    dim3 cw(DDIM * DDIM / 4 / 512, 8);       // (512, 8)   all weights, 2 f4/thr
    int ewBlocks  = (MROWS * DDIM / 8 + 255) / 256;   // comb: uint4
    int scBlocks  = (NCHAIN / 4 * CHUNKS) / 256;      // 256
    const size_t WN = (size_t)DDIM * DDIM;

    const float* FZ = (const float*)nullptr;
    float* FZo = (float*)nullptr;
    __half* HZ = (__half*)nullptr;

    // 0) convert all 8 weights to fp16 slots:
    //    0:W_lin 1:W_conv 2:Wa 3:Wx 4:W_lin2 5:W1 6:W2 7:W3
    conv_all_w_kernel<<<cw, 256>>>(W_lin, W_conv, Wa, Wx, W_lin2, W1, W2, W3, Wf);
    // 1) Af = fp16(rmsnorm(x, g1))
    rmsnorm_f16_kernel<<<MROWS / 4, 256>>>(x, g1, Af);
    // 2) lin(fp16 Af2) = xn @ W_lin^T + b_lin
    fgemm_kernel<<<gg1, 256, FGEMM_SMEM>>>(Af, Wf, b_lin, FZ, FZo, 0, Af2, FZ, FZo, HZ);
    // 3) rg(fp16 Af) = lin @ W_conv^T + b_conv
    fgemm_kernel<<<gg1, 256, FGEMM_SMEM>>>(Af2, Wf + WN, b_conv, FZ, FZo, 0, Af, FZ, FZo, HZ);
    // 4) merged: rt16 = rg @ Wa^T + ba ; it16 = rg @ Wx^T + bx  (slots 2,3)
    fgemm_kernel<<<gg2, 256, FGEMM_SMEM>>>(Af, Wf + 2 * WN, ba, FZ, FZo, 0, rt16, bx, FZo, it16);
    // 5-7) chunked scan: gateprep + local scan, aggregate scan, carry + gelu*h
    scan1_kernel<<<scBlocks, 256>>>(rt16, it16, Af, Lam, hl, Acar, Hcar);
    scan2_kernel<<<NCHAIN / 256, 256>>>(Acar, Hcar, carry);
    scan3_kernel<<<scBlocks, 256>>>(rt16, hl, carry, Lam, Af2);
    // 8) res = (gelu(lin)*h) @ W_lin2^T + b_lin2 + x   (slot 4)
    fgemm_kernel<<<gg1, 256, FGEMM_SMEM>>>(Af2, Wf + 4 * WN, b_lin2, x, res, 1, HZ, FZ, FZo, HZ);
    // 9) Af = fp16(rmsnorm(res, g2))
    rmsnorm_f16_kernel<<<MROWS / 4, 256>>>(res, g2, Af);
    // 10) merged: rt16 = xm @ W1^T + b1 ; it16 = xm @ W2^T + b2  (slots 5,6)
    fgemm_kernel<<<gg2, 256, FGEMM_SMEM>>>(Af, Wf + 5 * WN, b1, FZ, FZo, 0, rt16, b2, FZo, it16);
    // 11) Af2 = fp16(gelu(sigmoid(rt)) * it)
    comb_f16_kernel<<<ewBlocks, 256>>>(rt16, it16, Af2);
    // 12) out = combined @ W3^T + b3 + res   (slot 7)
    fgemm_kernel<<<gg1, 256, FGEMM_SMEM>>>(Af2, Wf + 7 * WN, b3, res, out, 1, HZ, FZ, FZo, HZ);

    (void)in_sizes; (void)n_in; (void)out_size;
}

// round 14
// speedup vs baseline: 1.1113x; 1.0263x over previous
#include <cuda_runtime.h>
#include <cuda_fp16.h>
#include <math.h>
#include <cstdint>

// Problem dims
#define MROWS 16384   // B*T = 4*4096
#define DDIM  1024
#define TLEN  4096
#define CHUNKS 64
#define CHLEN  (TLEN / CHUNKS)   // 64
#define NCHAIN 4096              // B * D

// ---------------- scratch (device globals; no allocation allowed) ----------
__device__ float g_res[MROWS * DDIM];
__device__ __half g_hl [MROWS * DDIM];
__device__ __half g_Af  [MROWS * DDIM];
__device__ __half g_Af2 [MROWS * DDIM];
__device__ __half g_rt16[MROWS * DDIM];
__device__ __half g_g16 [MROWS * DDIM];
__device__ __half g_Wf [8 * DDIM * DDIM];   // 8 weight slots
__device__ float g_Acar[NCHAIN * CHUNKS];
__device__ float g_Hcar[NCHAIN * CHUNKS];
__device__ float g_carry[NCHAIN * CHUNKS];

// ---------------- base-ISA tensor helpers ----------------------------------
__device__ __forceinline__ uint32_t smem_to_u32(const void* p) {
    uint32_t a;
    asm("{ .reg .u64 t; cvta.to.shared.u64 t, %1; cvt.u32.u64 %0, t; }"
        : "=r"(a) : "l"(p));
    return a;
}
__device__ __forceinline__ void cpasync16(uint32_t dst, const void* src) {
    asm volatile("cp.async.cg.shared.global [%0], [%1], 16;"
                 :: "r"(dst), "l"(src) : "memory");
}
#define CP_COMMIT() asm volatile("cp.async.commit_group;" ::: "memory")
#define CP_WAIT(n)  asm volatile("cp.async.wait_group %0;" :: "n"(n) : "memory")

__device__ __forceinline__ void ldsm4(uint32_t addr, uint32_t* r) {
    asm volatile("ldmatrix.sync.aligned.m8n8.x4.shared.b16 {%0,%1,%2,%3}, [%4];"
                 : "=r"(r[0]), "=r"(r[1]), "=r"(r[2]), "=r"(r[3]) : "r"(addr));
}
__device__ __forceinline__ void mma16816h(float* c, const uint32_t* a, const uint32_t* b) {
    asm volatile(
        "mma.sync.aligned.m16n8k16.row.col.f32.f16.f16.f32 "
        "{%0,%1,%2,%3}, {%4,%5,%6,%7}, {%8,%9}, {%0,%1,%2,%3};"
        : "+f"(c[0]), "+f"(c[1]), "+f"(c[2]), "+f"(c[3])
        : "r"(a[0]), "r"(a[1]), "r"(a[2]), "r"(a[3]), "r"(b[0]), "r"(b[1]));
}

// ---------------- math helpers ---------------------------------------------
__device__ __forceinline__ float gelu_exact(float x) {
    return 0.5f * x * (1.0f + erff(x * 0.70710678118654752440f));
}
__device__ __forceinline__ float sigmoidf_(float x) {
    return 1.0f / (1.0f + expf(-x));
}
__device__ __forceinline__ float h2lo(uint32_t u) {
    __half2 h = *(__half2*)&u;
    return __low2float(h);
}
__device__ __forceinline__ float h2hi(uint32_t u) {
    __half2 h = *(__half2*)&u;
    return __high2float(h);
}
__device__ __forceinline__ uint32_t pack2h(float a, float b) {
    __half2 h = __floats2half2_rn(a, b);
    return *(uint32_t*)&h;
}

// ---------------- fp32 -> fp16 convert: all 8 weights, MLP=2 ---------------
__global__ void conv_all_w_kernel(const float* __restrict__ w0, const float* __restrict__ w1,
                                  const float* __restrict__ w2, const float* __restrict__ w3,
                                  const float* __restrict__ w4, const float* __restrict__ w5,
                                  const float* __restrict__ w6, const float* __restrict__ w7,
                                  __half* __restrict__ dst) {
    const float* srcs[8] = {w0, w1, w2, w3, w4, w5, w6, w7};
    int slot = blockIdx.y;
    const float* src = srcs[slot];
    __half* d = dst + (size_t)slot * DDIM * DDIM;
    int i = (blockIdx.x * 256 + threadIdx.x) * 2;     // 2 float4 per thread
    float4 v0 = ((const float4*)src)[i];
    float4 v1 = ((const float4*)src)[i + 1];
    ((__half2*)d)[2 * i]     = __floats2half2_rn(v0.x, v0.y);
    ((__half2*)d)[2 * i + 1] = __floats2half2_rn(v0.z, v0.w);
    ((__half2*)d)[2 * i + 2] = __floats2half2_rn(v1.x, v1.y);
    ((__half2*)d)[2 * i + 3] = __floats2half2_rn(v1.z, v1.w);
}

// ---------------- fp16 1-term mma.sync GEMM, BN=128, 2-stage ---------------
#define F_TILE_A 16384               // 128 x 64 fp16
#define F_TILE_B 16384               // 128 x 64 fp16
#define F_STAGE  32768
#define NCHUNK (DDIM / 64)           // 16

__device__ __forceinline__ uint32_t swaddr(uint32_t tile, uint32_t row, uint32_t kb) {
    uint32_t off = row * 128u + kb;
    return tile + (off ^ ((off >> 3) & 0x70u));
}

__global__ void __launch_bounds__(256, 2)
fgemm_kernel(const __half* __restrict__ Af, const __half* __restrict__ Bf,
             const float* __restrict__ bias, const float* __restrict__ addp,
             float* __restrict__ C, int doAdd,
             __half* __restrict__ Sf) {
    extern __shared__ __align__(1024) char smem_raw[];
    uint32_t smem0 = smem_to_u32(smem_raw);
    uint32_t tbase = (smem0 + 1023u) & ~1023u;

    int tid = threadIdx.x;
    int wid = tid >> 5;
    int lane = tid & 31;
    int m0 = blockIdx.y * 128;
    int n0 = blockIdx.x * 128;

    int row_base = tid >> 3;        // 0..31
    int col = tid & 7;
    const char* srcb[8];
    uint32_t stsoff[8];
    {
        const char* aB = (const char*)(Af + (size_t)m0 * DDIM);
        const char* bB = (const char*)(Bf + (size_t)n0 * DDIM);
        #pragma unroll
        for (int i = 0; i < 4; i++) {
            uint32_t rr = (uint32_t)row_base + 32u * i;
            srcb[i] = aB + (size_t)rr * 2048 + col * 16;
            uint32_t off = rr * 128u + (uint32_t)col * 16u;
            stsoff[i] = off ^ ((off >> 3) & 0x70u);
        }
        #pragma unroll
        for (int i = 4; i < 8; i++) {
            uint32_t rr = (uint32_t)row_base + 32u * (i - 4);
            srcb[i] = bB + (size_t)rr * 2048 + col * 16;
            uint32_t off = rr * 128u + (uint32_t)col * 16u;
            stsoff[i] = F_TILE_A + (off ^ ((off >> 3) & 0x70u));
        }
    }

    #define F_ISSUE(buf, chunk) do { \
        uint32_t db_ = tbase + (uint32_t)(buf) * F_STAGE; \
        _Pragma("unroll") \
        for (int i_ = 0; i_ < 8; i_++) \
            cpasync16(db_ + stsoff[i_], srcb[i_] + (size_t)(chunk) * 128); \
        CP_COMMIT(); \
    } while (0)

    int warp_m = wid & 3;
    int warp_n = wid >> 2;          // 0..1
    uint32_t ar  = (uint32_t)((lane & 7) + ((lane >> 3) & 1) * 8);
    uint32_t akb = (uint32_t)(((lane >> 4) & 1) * 16);
    uint32_t br  = (uint32_t)((lane & 7) + ((lane >> 4) & 1) * 8);
    uint32_t bkb = (uint32_t)(((lane >> 3) & 1) * 16);

    float acc[2][8][4];
    #pragma unroll
    for (int i = 0; i < 2; i++)
        #pragma unroll
        for (int j = 0; j < 8; j++)
            #pragma unroll
            for (int q = 0; q < 4; q++) acc[i][j][q] = 0.0f;

    F_ISSUE(0, 0);

    for (int c = 0; c < NCHUNK; c++) {
        CP_WAIT(0);
        __syncthreads();
        if (c + 1 < NCHUNK) F_ISSUE((c + 1) & 1, c + 1);

        uint32_t sb = tbase + (uint32_t)(c & 1) * F_STAGE;
        uint32_t tAf = sb;
        uint32_t tBf = sb + F_TILE_A;

        #pragma unroll
        for (int k16 = 0; k16 < 4; k16++) {
            uint32_t kb = (uint32_t)k16 * 32u;
            uint32_t af[2][4], bf[4][4];
            #pragma unroll
            for (int mt = 0; mt < 2; mt++)
                ldsm4(swaddr(tAf, (uint32_t)(warp_m * 32 + mt * 16) + ar, kb + akb), af[mt]);
            #pragma unroll
            for (int p = 0; p < 4; p++)
                ldsm4(swaddr(tBf, (uint32_t)(warp_n * 64 + p * 16) + br, kb + bkb), bf[p]);
            #pragma unroll
            for (int mt = 0; mt < 2; mt++)
                #pragma unroll
                for (int p = 0; p < 4; p++) {
                    mma16816h(acc[mt][2 * p],     af[mt], &bf[p][0]);
                    mma16816h(acc[mt][2 * p + 1], af[mt], &bf[p][2]);
                }
        }
    }

    int lm = lane >> 2;
    int lc = (lane & 3) * 2;
    int cm = m0 + warp_m * 32;
    int cn = n0 + warp_n * 64;
    #pragma unroll
    for (int mt = 0; mt < 2; mt++) {
        #pragma unroll
        for (int nt = 0; nt < 8; nt++) {
            int r0 = cm + mt * 16 + lm;
            int cc = cn + nt * 8 + lc;
            float2 bv = *(const float2*)&bias[cc];
            float* a = acc[mt][nt];
            float2 o0 = make_float2(a[0] + bv.x, a[1] + bv.y);
            float2 o1 = make_float2(a[2] + bv.x, a[3] + bv.y);
            size_t off0 = (size_t)r0 * DDIM + cc;
            size_t off1 = (size_t)(r0 + 8) * DDIM + cc;
            if (doAdd) {
                float2 q0 = *(const float2*)(addp + off0);
                float2 q1 = *(const float2*)(addp + off1);
                o0.x += q0.x; o0.y += q0.y;
                o1.x += q1.x; o1.y += q1.y;
            }
            if (C) {
                *(float2*)(C + off0) = o0;
                *(float2*)(C + off1) = o1;
            }
            if (Sf) {
                *(__half2*)(Sf + off0) = __floats2half2_rn(o0.x, o0.y);
                *(__half2*)(Sf + off1) = __floats2half2_rn(o1.x, o1.y);
            }
        }
    }
}

// ---------------- dual-weight fused GEMM -----------------------------------
// CTA tile 128(M) x 64(N) over TWO weights sharing A and the column range.
// Stage: A 16KB + B1 8KB + B2 8KB = 32KB. 256 threads, 2 CTAs/SM.
// mode 0 (COMB): O1 <- fp16( gelu(sigmoid(v1)) * v2 )
// mode 1 (GATE): O1 <- fp16(v1) ; O2 <- fp16( sqrt(1-a^2)*sigmoid(v2)*rg ),
//                a = exp(la * sigmoid(v1) / 8), la from Lam, rg from rgbuf.
#define D_TILE_B 8192

__global__ void __launch_bounds__(256, 2)
fgemm_dual_kernel(const __half* __restrict__ Af,
                  const __half* __restrict__ B1, const __half* __restrict__ B2,
                  const float* __restrict__ bias1, const float* __restrict__ bias2,
                  int mode,
                  __half* __restrict__ O1, __half* __restrict__ O2,
                  const float* __restrict__ Lam, const __half* __restrict__ rgbuf) {
    extern __shared__ __align__(1024) char smem_raw[];
    uint32_t smem0 = smem_to_u32(smem_raw);
    uint32_t tbase = (smem0 + 1023u) & ~1023u;

    int tid = threadIdx.x;
    int wid = tid >> 5;
    int lane = tid & 31;
    int m0 = blockIdx.y * 128;
    int n0 = blockIdx.x * 64;

    int row_base = tid >> 3;        // 0..31
    int col = tid & 7;
    const char* srcb[8];
    uint32_t stsoff[8];
    {
        const char* aB  = (const char*)(Af + (size_t)m0 * DDIM);
        const char* b1B = (const char*)(B1 + (size_t)n0 * DDIM);
        const char* b2B = (const char*)(B2 + (size_t)n0 * DDIM);
        #pragma unroll
        for (int i = 0; i < 4; i++) {
            uint32_t rr = (uint32_t)row_base + 32u * i;
            srcb[i] = aB + (size_t)rr * 2048 + col * 16;
            uint32_t off = rr * 128u + (uint32_t)col * 16u;
            stsoff[i] = off ^ ((off >> 3) & 0x70u);
        }
        #pragma unroll
        for (int i = 4; i < 6; i++) {
            uint32_t rr = (uint32_t)row_base + 32u * (i - 4);
            srcb[i] = b1B + (size_t)rr * 2048 + col * 16;
            uint32_t off = rr * 128u + (uint32_t)col * 16u;
            stsoff[i] = F_TILE_A + (off ^ ((off >> 3) & 0x70u));
        }
        #pragma unroll
        for (int i = 6; i < 8; i++) {
            uint32_t rr = (uint32_t)row_base + 32u * (i - 6);
            srcb[i] = b2B + (size_t)rr * 2048 + col * 16;
            uint32_t off = rr * 128u + (uint32_t)col * 16u;
            stsoff[i] = F_TILE_A + D_TILE_B + (off ^ ((off >> 3) & 0x70u));
        }
    }

    #define D_ISSUE(buf, chunk) do { \
        uint32_t db_ = tbase + (uint32_t)(buf) * F_STAGE; \
        _Pragma("unroll") \
        for (int i_ = 0; i_ < 8; i_++) \
            cpasync16(db_ + stsoff[i_], srcb[i_] + (size_t)(chunk) * 128); \
        CP_COMMIT(); \
    } while (0)

    int warp_m = wid & 3;
    int warp_n = wid >> 2;          // 0..1 (32-col halves)
    uint32_t ar  = (uint32_t)((lane & 7) + ((lane >> 3) & 1) * 8);
    uint32_t akb = (uint32_t)(((lane >> 4) & 1) * 16);
    uint32_t br  = (uint32_t)((lane & 7) + ((lane >> 4) & 1) * 8);
    uint32_t bkb = (uint32_t)(((lane >> 3) & 1) * 16);

    float acc1[2][4][4], acc2[2][4][4];
    #pragma unroll
    for (int i = 0; i < 2; i++)
        #pragma unroll
        for (int j = 0; j < 4; j++)
            #pragma unroll
            for (int q = 0; q < 4; q++) { acc1[i][j][q] = 0.0f; acc2[i][j][q] = 0.0f; }

    D_ISSUE(0, 0);

    for (int c = 0; c < NCHUNK; c++) {
        CP_WAIT(0);
        __syncthreads();
        if (c + 1 < NCHUNK) D_ISSUE((c + 1) & 1, c + 1);

        uint32_t sb = tbase + (uint32_t)(c & 1) * F_STAGE;
        uint32_t tAf = sb;
        uint32_t tB1 = sb + F_TILE_A;
        uint32_t tB2 = sb + F_TILE_A + D_TILE_B;

        #pragma unroll
        for (int k16 = 0; k16 < 4; k16++) {
            uint32_t kb = (uint32_t)k16 * 32u;
            uint32_t af[2][4], bf1[2][4], bf2[2][4];
            #pragma unroll
            for (int mt = 0; mt < 2; mt++)
                ldsm4(swaddr(tAf, (uint32_t)(warp_m * 32 + mt * 16) + ar, kb + akb), af[mt]);
            #pragma unroll
            for (int p = 0; p < 2; p++)
                ldsm4(swaddr(tB1, (uint32_t)(warp_n * 32 + p * 16) + br, kb + bkb), bf1[p]);
            #pragma unroll
            for (int p = 0; p < 2; p++)
                ldsm4(swaddr(tB2, (uint32_t)(warp_n * 32 + p * 16) + br, kb + bkb), bf2[p]);
            #pragma unroll
            for (int mt = 0; mt < 2; mt++)
                #pragma unroll
                for (int p = 0; p < 2; p++) {
                    mma16816h(acc1[mt][2 * p],     af[mt], &bf1[p][0]);
                    mma16816h(acc1[mt][2 * p + 1], af[mt], &bf1[p][2]);
                    mma16816h(acc2[mt][2 * p],     af[mt], &bf2[p][0]);
                    mma16816h(acc2[mt][2 * p + 1], af[mt], &bf2[p][2]);
                }
        }
    }

    int lm = lane >> 2;
    int lc = (lane & 3) * 2;
    int cm = m0 + warp_m * 32;
    int cn = n0 + warp_n * 32;
    #pragma unroll
    for (int mt = 0; mt < 2; mt++) {
        #pragma unroll
        for (int nt = 0; nt < 4; nt++) {
            int r0 = cm + mt * 16 + lm;
            int cc = cn + nt * 8 + lc;
            float2 b1v = *(const float2*)&bias1[cc];
            float2 b2v = *(const float2*)&bias2[cc];
            float* a1 = acc1[mt][nt];
            float* a2 = acc2[mt][nt];
            size_t off0 = (size_t)r0 * DDIM + cc;
            size_t off1 = (size_t)(r0 + 8) * DDIM + cc;
            float v1r0x = a1[0] + b1v.x, v1r0y = a1[1] + b1v.y;
            float v1r1x = a1[2] + b1v.x, v1r1y = a1[3] + b1v.y;
            float v2r0x = a2[0] + b2v.x, v2r0y = a2[1] + b2v.y;
            float v2r1x = a2[2] + b2v.x, v2r1y = a2[3] + b2v.y;
            if (mode == 0) {
                // comb: gelu(sigmoid(v1)) * v2
                *(__half2*)(O1 + off0) = __floats2half2_rn(
                    gelu_exact(sigmoidf_(v1r0x)) * v2r0x,
                    gelu_exact(sigmoidf_(v1r0y)) * v2r0y);
                *(__half2*)(O1 + off1) = __floats2half2_rn(
                    gelu_exact(sigmoidf_(v1r1x)) * v2r1x,
                    gelu_exact(sigmoidf_(v1r1y)) * v2r1y);
            } else {
                // gate: O1 = rt(pre-act), O2 = sqrt(1-a^2)*sigmoid(v2)*rg
                float2 lam = *(const float2*)&Lam[cc];
                float la0 = -log1pf(expf(-lam.x));
                float la1 = -log1pf(expf(-lam.y));
                __half2 rg0 = *(const __half2*)(rgbuf + off0);
                __half2 rg1 = *(const __half2*)(rgbuf + off1);
                float a0 = expf(la0 * sigmoidf_(v1r0x) * 0.125f);
                float a1_ = expf(la1 * sigmoidf_(v1r0y) * 0.125f);
                float a2_ = expf(la0 * sigmoidf_(v1r1x) * 0.125f);
                float a3_ = expf(la1 * sigmoidf_(v1r1y) * 0.125f);
                float g0 = sqrtf(fmaxf(1.0f - a0 * a0, 0.0f)) * sigmoidf_(v2r0x) * __low2float(rg0);
                float g1 = sqrtf(fmaxf(1.0f - a1_ * a1_, 0.0f)) * sigmoidf_(v2r0y) * __high2float(rg0);
                float g2 = sqrtf(fmaxf(1.0f - a2_ * a2_, 0.0f)) * sigmoidf_(v2r1x) * __low2float(rg1);
                float g3 = sqrtf(fmaxf(1.0f - a3_ * a3_, 0.0f)) * sigmoidf_(v2r1y) * __high2float(rg1);
                *(__half2*)(O1 + off0) = __floats2half2_rn(v1r0x, v1r0y);
                *(__half2*)(O1 + off1) = __floats2half2_rn(v1r1x, v1r1y);
                *(__half2*)(O2 + off0) = __floats2half2_rn(g0, g1);
                *(__half2*)(O2 + off1) = __floats2half2_rn(g2, g3);
            }
        }
    }
}

// ---------------- rmsnorm -> fp16, 4 rows per block (MLP=4) ----------------
__global__ void rmsnorm_f16_kernel(const float* __restrict__ x,
                                   const float* __restrict__ gw,
                                   __half* __restrict__ Sf) {
    int row0 = blockIdx.x * 4;
    int tid = threadIdx.x;
    float4 v[4];
    #pragma unroll
    for (int j = 0; j < 4; j++)
        v[j] = ((const float4*)(x + (size_t)(row0 + j) * DDIM))[tid];
    float4 g = ((const float4*)gw)[tid];

    float ps[4];
    #pragma unroll
    for (int j = 0; j < 4; j++)
        ps[j] = v[j].x * v[j].x + v[j].y * v[j].y + v[j].z * v[j].z + v[j].w * v[j].w;
    #pragma unroll
    for (int j = 0; j < 4; j++)
        #pragma unroll
        for (int o = 16; o > 0; o >>= 1)
            ps[j] += __shfl_xor_sync(0xffffffffu, ps[j], o);

    __shared__ float sred[4][8];
    if ((tid & 31) == 0)
        #pragma unroll
        for (int j = 0; j < 4; j++) sred[j][tid >> 5] = ps[j];
    __syncthreads();
    float s[4];
    #pragma unroll
    for (int j = 0; j < 4; j++) {
        float total = 0.0f;
        #pragma unroll
        for (int i = 0; i < 8; i++) total += sred[j][i];
        s[j] = 32.0f / fmaxf(sqrtf(total), 1e-12f);
    }
    #pragma unroll
    for (int j = 0; j < 4; j++) {
        float o0 = v[j].x * s[j] * g.x, o1 = v[j].y * s[j] * g.y;
        float o2 = v[j].z * s[j] * g.z, o3 = v[j].w * s[j] * g.w;
        size_t base2 = (size_t)(row0 + j) * (DDIM / 2) + tid * 2;
        ((__half2*)Sf)[base2]     = __floats2half2_rn(o0, o1);
        ((__half2*)Sf)[base2 + 1] = __floats2half2_rn(o2, o3);
    }
}

// ---------------- chunked RG-LRU scan (4 chains/thread, uint2) -------------
// pass 1: local scan with precomputed gated input g16
__global__ void scan1_kernel(const __half* __restrict__ rt, const __half* __restrict__ gt,
                             const float* __restrict__ Lam,
                             __half* __restrict__ hl,
                             float* __restrict__ Acar, float* __restrict__ Hcar) {
    int i = blockIdx.x * 256 + threadIdx.x;     // 0 .. 65535 (quads x chunks)
    int q = i & 1023;
    int chunk = i >> 10;
    int b = q >> 8;
    int dq = q & 255;
    size_t base4 = (((size_t)b * TLEN + (size_t)chunk * CHLEN) * DDIM) / 4 + dq;
    float la[4];
    {
        float4 lam = *(const float4*)&Lam[4 * dq];
        la[0] = -log1pf(expf(-lam.x)); la[1] = -log1pf(expf(-lam.y));
        la[2] = -log1pf(expf(-lam.z)); la[3] = -log1pf(expf(-lam.w));
    }
    float h[4] = {0, 0, 0, 0}, P[4] = {1, 1, 1, 1};
    const uint2* rt4 = (const uint2*)rt;
    const uint2* gt4 = (const uint2*)gt;
    uint2* hl4 = (uint2*)hl;
    #pragma unroll 4
    for (int t = 0; t < CHLEN; t++) {
        size_t a_ = base4 + (size_t)t * (DDIM / 4);
        uint2 rv = rt4[a_], gv = gt4[a_];
        float rr[4] = {h2lo(rv.x), h2hi(rv.x), h2lo(rv.y), h2hi(rv.y)};
        float gg[4] = {h2lo(gv.x), h2hi(gv.x), h2lo(gv.y), h2hi(gv.y)};
        #pragma unroll
        for (int j = 0; j < 4; j++) {
            float a = expf(la[j] * sigmoidf_(rr[j]) * 0.125f);
            h[j] = fmaf(a, h[j], gg[j]);
            P[j] *= a;
        }
        uint2 ho;
        ho.x = pack2h(h[0], h[1]);
        ho.y = pack2h(h[2], h[3]);
        hl4[a_] = ho;
    }
    int chain = b * DDIM + 4 * dq;
    #pragma unroll
    for (int j = 0; j < 4; j++) {
        Acar[chunk * NCHAIN + chain + j] = P[j];
        Hcar[chunk * NCHAIN + chain + j] = h[j];
    }
}

// pass 2: serial scan over chunk aggregates (per chain)
__global__ void scan2_kernel(const float* __restrict__ Acar, const float* __restrict__ Hcar,
                             float* __restrict__ carry) {
    int chain = blockIdx.x * 256 + threadIdx.x;   // 0..4095
    float h = 0.0f;
    #pragma unroll
    for (int c = 0; c < CHUNKS; c++) {
        int idx = c * NCHAIN + chain;
        carry[idx] = h;
        h = fmaf(Acar[idx], h, Hcar[idx]);
    }
}

// pass 3: apply carry, fused gelu(lin)*h, fp16 in-place on lin buffer
__global__ void scan3_kernel(const __half* __restrict__ rt, const __half* __restrict__ hl,
                             const float* __restrict__ carry,
                             const float* __restrict__ Lam,
                             __half* __restrict__ linSf) {
    int i = blockIdx.x * 256 + threadIdx.x;     // 0 .. 65535
    int q = i & 1023;
    int chunk = i >> 10;
    int b = q >> 8;
    int dq = q & 255;
    size_t base4 = (((size_t)b * TLEN + (size_t)chunk * CHLEN) * DDIM) / 4 + dq;
    float la[4];
    {
        float4 lam = *(const float4*)&Lam[4 * dq];
        la[0] = -log1pf(expf(-lam.x)); la[1] = -log1pf(expf(-lam.y));
        la[2] = -log1pf(expf(-lam.z)); la[3] = -log1pf(expf(-lam.w));
    }
    int chain = b * DDIM + 4 * dq;
    float cin[4], P[4] = {1, 1, 1, 1};
    #pragma unroll
    for (int j = 0; j < 4; j++) cin[j] = carry[chunk * NCHAIN + chain + j];
    const uint2* rt4 = (const uint2*)rt;
    const uint2* hl4 = (const uint2*)hl;
    uint2* ls4 = (uint2*)linSf;
    #pragma unroll 4
    for (int t = 0; t < CHLEN; t++) {
        size_t a_ = base4 + (size_t)t * (DDIM / 4);
        uint2 rv = rt4[a_], hv = hl4[a_], lv = ls4[a_];
        float rr[4] = {h2lo(rv.x), h2hi(rv.x), h2lo(rv.y), h2hi(rv.y)};
        float hh[4] = {h2lo(hv.x), h2hi(hv.x), h2lo(hv.y), h2hi(hv.y)};
        float ll[4] = {h2lo(lv.x), h2hi(lv.x), h2lo(lv.y), h2hi(lv.y)};
        float oo[4];
        #pragma unroll
        for (int j = 0; j < 4; j++) {
            float a = expf(la[j] * sigmoidf_(rr[j]) * 0.125f);
            P[j] *= a;
            float h = fmaf(P[j], cin[j], hh[j]);
            oo[j] = gelu_exact(ll[j]) * h;
        }
        uint2 o;
        o.x = pack2h(oo[0], oo[1]);
        o.y = pack2h(oo[2], oo[3]);
        ls4[a_] = o;
    }
}

// ---------------- launch ---------------------------------------------------
extern "C" void kernel_launch(void* const* d_in, const int* in_sizes, int n_in,
                              void* d_out, int out_size) {
    const float* x      = (const float*)d_in[0];
    const float* g1     = (const float*)d_in[1];
    const float* g2     = (const float*)d_in[2];
    const float* W_lin  = (const float*)d_in[3];
    const float* b_lin  = (const float*)d_in[4];
    const float* W_conv = (const float*)d_in[5];
    const float* b_conv = (const float*)d_in[6];
    const float* W_lin2 = (const float*)d_in[7];
    const float* b_lin2 = (const float*)d_in[8];
    const float* Wa     = (const float*)d_in[9];
    const float* ba     = (const float*)d_in[10];
    const float* Wx     = (const float*)d_in[11];
    const float* bx     = (const float*)d_in[12];
    const float* Lam    = (const float*)d_in[13];
    const float* W1     = (const float*)d_in[14];
    const float* b1     = (const float*)d_in[15];
    const float* W2     = (const float*)d_in[16];
    const float* b2     = (const float*)d_in[17];
    const float* W3     = (const float*)d_in[18];
    const float* b3     = (const float*)d_in[19];
    float* out = (float*)d_out;

    float *res, *Acar, *Hcar, *carry;
    __half *hl, *Af, *Af2, *rt16, *g16, *Wf;
    cudaGetSymbolAddress((void**)&res, g_res);
    cudaGetSymbolAddress((void**)&hl,  g_hl);
    cudaGetSymbolAddress((void**)&Acar, g_Acar);
    cudaGetSymbolAddress((void**)&Hcar, g_Hcar);
    cudaGetSymbolAddress((void**)&carry, g_carry);
    cudaGetSymbolAddress((void**)&Af,   g_Af);
    cudaGetSymbolAddress((void**)&Af2,  g_Af2);
    cudaGetSymbolAddress((void**)&rt16, g_rt16);
    cudaGetSymbolAddress((void**)&g16,  g_g16);
    cudaGetSymbolAddress((void**)&Wf,   g_Wf);

    const int FGEMM_SMEM = 2 * F_STAGE + 1024;   // 66560
    cudaFuncSetAttribute(fgemm_kernel,
                         cudaFuncAttributeMaxDynamicSharedMemorySize, FGEMM_SMEM);
    cudaFuncSetAttribute(fgemm_dual_kernel,
                         cudaFuncAttributeMaxDynamicSharedMemorySize, FGEMM_SMEM);

    dim3 gg1(DDIM / 128, MROWS / 128);       // (8, 128)   singles
    dim3 ggd(DDIM / 64, MROWS / 128);        // (16, 128)  duals
    dim3 cw(DDIM * DDIM / 4 / 512, 8);       // (512, 8)   all weights
    int scBlocks  = (NCHAIN / 4 * CHUNKS) / 256;      // 256
    const size_t WN = (size_t)DDIM * DDIM;

    const float* FZ = (const float*)nullptr;
    float* FZo = (float*)nullptr;
    __half* HZ = (__half*)nullptr;

    // 0) convert all 8 weights: 0:W_lin 1:W_conv 2:Wa 3:Wx 4:W_lin2 5:W1 6:W2 7:W3
    conv_all_w_kernel<<<cw, 256>>>(W_lin, W_conv, Wa, Wx, W_lin2, W1, W2, W3, Wf);
    // 1) Af = fp16(rmsnorm(x, g1))
    rmsnorm_f16_kernel<<<MROWS / 4, 256>>>(x, g1, Af);
    // 2) lin(fp16 Af2) = xn @ W_lin^T + b_lin
    fgemm_kernel<<<gg1, 256, FGEMM_SMEM>>>(Af, Wf, b_lin, FZ, FZo, 0, Af2);
    // 3) rg(fp16 Af) = lin @ W_conv^T + b_conv
    fgemm_kernel<<<gg1, 256, FGEMM_SMEM>>>(Af2, Wf + WN, b_conv, FZ, FZo, 0, Af);
    // 4) dual GATE: rt16 = rg@Wa^T+ba (pre-act) ; g16 = sqrt(1-a^2)*sig(rg@Wx^T+bx)*rg
    fgemm_dual_kernel<<<ggd, 256, FGEMM_SMEM>>>(Af, Wf + 2 * WN, Wf + 3 * WN,
                                                ba, bx, 1, rt16, g16, Lam, Af);
    // 5-7) chunked scan
    scan1_kernel<<<scBlocks, 256>>>(rt16, g16, Lam, hl, Acar, Hcar);
    scan2_kernel<<<NCHAIN / 256, 256>>>(Acar, Hcar, carry);
    scan3_kernel<<<scBlocks, 256>>>(rt16, hl, carry, Lam, Af2);
    // 8) res = (gelu(lin)*h) @ W_lin2^T + b_lin2 + x   (slot 4)
    fgemm_kernel<<<gg1, 256, FGEMM_SMEM>>>(Af2, Wf + 4 * WN, b_lin2, x, res, 1, HZ);
    // 9) Af = fp16(rmsnorm(res, g2))
    rmsnorm_f16_kernel<<<MROWS / 4, 256>>>(res, g2, Af);
    // 10) dual COMB: Af2 = gelu(sig(xm@W1^T+b1)) * (xm@W2^T+b2)   (slots 5,6)
    fgemm_dual_kernel<<<ggd, 256, FGEMM_SMEM>>>(Af, Wf + 5 * WN, Wf + 6 * WN,
                                                b1, b2, 0, Af2, HZ, FZ, HZ);
    // 12) out = combined @ W3^T + b3 + res   (slot 7)
    fgemm_kernel<<<gg1, 256, FGEMM_SMEM>>>(Af2, Wf + 7 * WN, b3, res, out, 1, HZ);

    (void)in_sizes; (void)n_in; (void)out_size;
}

// round 15
// speedup vs baseline: 1.1187x; 1.0066x over previous
#include <cuda_runtime.h>
#include <cuda_fp16.h>
#include <math.h>
#include <cstdint>

// Problem dims
#define MROWS 16384   // B*T = 4*4096
#define DDIM  1024
#define TLEN  4096
#define CHUNKS 64
#define CHLEN  (TLEN / CHUNKS)   // 64
#define NCHAIN 4096              // B * D

// ---------------- scratch (device globals; no allocation allowed) ----------
__device__ __half g_res16[MROWS * DDIM];
__device__ __half g_hl [MROWS * DDIM];
__device__ __half g_Af  [MROWS * DDIM];
__device__ __half g_Af2 [MROWS * DDIM];
__device__ __half g_rt16[MROWS * DDIM];
__device__ __half g_g16 [MROWS * DDIM];
__device__ __half g_Wf [8 * DDIM * DDIM];   // 8 weight slots
__device__ float g_Acar[NCHAIN * CHUNKS];
__device__ float g_Hcar[NCHAIN * CHUNKS];
__device__ float g_carry[NCHAIN * CHUNKS];

// ---------------- base-ISA tensor helpers ----------------------------------
__device__ __forceinline__ uint32_t smem_to_u32(const void* p) {
    uint32_t a;
    asm("{ .reg .u64 t; cvta.to.shared.u64 t, %1; cvt.u32.u64 %0, t; }"
        : "=r"(a) : "l"(p));
    return a;
}
__device__ __forceinline__ void cpasync16(uint32_t dst, const void* src) {
    asm volatile("cp.async.cg.shared.global [%0], [%1], 16;"
                 :: "r"(dst), "l"(src) : "memory");
}
#define CP_COMMIT() asm volatile("cp.async.commit_group;" ::: "memory")
#define CP_WAIT(n)  asm volatile("cp.async.wait_group %0;" :: "n"(n) : "memory")

__device__ __forceinline__ void ldsm4(uint32_t addr, uint32_t* r) {
    asm volatile("ldmatrix.sync.aligned.m8n8.x4.shared.b16 {%0,%1,%2,%3}, [%4];"
                 : "=r"(r[0]), "=r"(r[1]), "=r"(r[2]), "=r"(r[3]) : "r"(addr));
}
__device__ __forceinline__ void mma16816h(float* c, const uint32_t* a, const uint32_t* b) {
    asm volatile(
        "mma.sync.aligned.m16n8k16.row.col.f32.f16.f16.f32 "
        "{%0,%1,%2,%3}, {%4,%5,%6,%7}, {%8,%9}, {%0,%1,%2,%3};"
        : "+f"(c[0]), "+f"(c[1]), "+f"(c[2]), "+f"(c[3])
        : "r"(a[0]), "r"(a[1]), "r"(a[2]), "r"(a[3]), "r"(b[0]), "r"(b[1]));
}

// ---------------- math helpers ---------------------------------------------
__device__ __forceinline__ float gelu_exact(float x) {
    return 0.5f * x * (1.0f + erff(x * 0.70710678118654752440f));
}
__device__ __forceinline__ float sigmoidf_(float x) {
    return 1.0f / (1.0f + expf(-x));
}
__device__ __forceinline__ float h2lo(uint32_t u) {
    __half2 h = *(__half2*)&u;
    return __low2float(h);
}
__device__ __forceinline__ float h2hi(uint32_t u) {
    __half2 h = *(__half2*)&u;
    return __high2float(h);
}
__device__ __forceinline__ uint32_t pack2h(float a, float b) {
    __half2 h = __floats2half2_rn(a, b);
    return *(uint32_t*)&h;
}

// ---------------- fp32 -> fp16 convert: all 8 weights, MLP=2 ---------------
__global__ void conv_all_w_kernel(const float* __restrict__ w0, const float* __restrict__ w1,
                                  const float* __restrict__ w2, const float* __restrict__ w3,
                                  const float* __restrict__ w4, const float* __restrict__ w5,
                                  const float* __restrict__ w6, const float* __restrict__ w7,
                                  __half* __restrict__ dst) {
    const float* srcs[8] = {w0, w1, w2, w3, w4, w5, w6, w7};
    int slot = blockIdx.y;
    const float* src = srcs[slot];
    __half* d = dst + (size_t)slot * DDIM * DDIM;
    int i = (blockIdx.x * 256 + threadIdx.x) * 2;     // 2 float4 per thread
    float4 v0 = ((const float4*)src)[i];
    float4 v1 = ((const float4*)src)[i + 1];
    ((__half2*)d)[2 * i]     = __floats2half2_rn(v0.x, v0.y);
    ((__half2*)d)[2 * i + 1] = __floats2half2_rn(v0.z, v0.w);
    ((__half2*)d)[2 * i + 2] = __floats2half2_rn(v1.x, v1.y);
    ((__half2*)d)[2 * i + 3] = __floats2half2_rn(v1.z, v1.w);
}

// ---------------- fp16 1-term mma.sync GEMM, BN=128, 2-stage ---------------
// doAdd: 0 = none, 1 = += addp (fp32), 2 = += addpH (fp16)
#define F_TILE_A 16384               // 128 x 64 fp16
#define F_TILE_B 16384               // 128 x 64 fp16
#define F_STAGE  32768
#define NCHUNK (DDIM / 64)           // 16

__device__ __forceinline__ uint32_t swaddr(uint32_t tile, uint32_t row, uint32_t kb) {
    uint32_t off = row * 128u + kb;
    return tile + (off ^ ((off >> 3) & 0x70u));
}

__global__ void __launch_bounds__(256, 2)
fgemm_kernel(const __half* __restrict__ Af, const __half* __restrict__ Bf,
             const float* __restrict__ bias,
             const float* __restrict__ addp, const __half* __restrict__ addpH,
             float* __restrict__ C, int doAdd,
             __half* __restrict__ Sf) {
    extern __shared__ __align__(1024) char smem_raw[];
    uint32_t smem0 = smem_to_u32(smem_raw);
    uint32_t tbase = (smem0 + 1023u) & ~1023u;

    int tid = threadIdx.x;
    int wid = tid >> 5;
    int lane = tid & 31;
    int m0 = blockIdx.y * 128;
    int n0 = blockIdx.x * 128;

    int row_base = tid >> 3;        // 0..31
    int col = tid & 7;
    const char* srcb[8];
    uint32_t stsoff[8];
    {
        const char* aB = (const char*)(Af + (size_t)m0 * DDIM);
        const char* bB = (const char*)(Bf + (size_t)n0 * DDIM);
        #pragma unroll
        for (int i = 0; i < 4; i++) {
            uint32_t rr = (uint32_t)row_base + 32u * i;
            srcb[i] = aB + (size_t)rr * 2048 + col * 16;
            uint32_t off = rr * 128u + (uint32_t)col * 16u;
            stsoff[i] = off ^ ((off >> 3) & 0x70u);
        }
        #pragma unroll
        for (int i = 4; i < 8; i++) {
            uint32_t rr = (uint32_t)row_base + 32u * (i - 4);
            srcb[i] = bB + (size_t)rr * 2048 + col * 16;
            uint32_t off = rr * 128u + (uint32_t)col * 16u;
            stsoff[i] = F_TILE_A + (off ^ ((off >> 3) & 0x70u));
        }
    }

    #define F_ISSUE(buf, chunk) do { \
        uint32_t db_ = tbase + (uint32_t)(buf) * F_STAGE; \
        _Pragma("unroll") \
        for (int i_ = 0; i_ < 8; i_++) \
            cpasync16(db_ + stsoff[i_], srcb[i_] + (size_t)(chunk) * 128); \
        CP_COMMIT(); \
    } while (0)

    int warp_m = wid & 3;
    int warp_n = wid >> 2;          // 0..1
    uint32_t ar  = (uint32_t)((lane & 7) + ((lane >> 3) & 1) * 8);
    uint32_t akb = (uint32_t)(((lane >> 4) & 1) * 16);
    uint32_t br  = (uint32_t)((lane & 7) + ((lane >> 4) & 1) * 8);
    uint32_t bkb = (uint32_t)(((lane >> 3) & 1) * 16);

    float acc[2][8][4];
    #pragma unroll
    for (int i = 0; i < 2; i++)
        #pragma unroll
        for (int j = 0; j < 8; j++)
            #pragma unroll
            for (int q = 0; q < 4; q++) acc[i][j][q] = 0.0f;

    F_ISSUE(0, 0);

    for (int c = 0; c < NCHUNK; c++) {
        CP_WAIT(0);
        __syncthreads();
        if (c + 1 < NCHUNK) F_ISSUE((c + 1) & 1, c + 1);

        uint32_t sb = tbase + (uint32_t)(c & 1) * F_STAGE;
        uint32_t tAf = sb;
        uint32_t tBf = sb + F_TILE_A;

        #pragma unroll
        for (int k16 = 0; k16 < 4; k16++) {
            uint32_t kb = (uint32_t)k16 * 32u;
            uint32_t af[2][4], bf[4][4];
            #pragma unroll
            for (int mt = 0; mt < 2; mt++)
                ldsm4(swaddr(tAf, (uint32_t)(warp_m * 32 + mt * 16) + ar, kb + akb), af[mt]);
            #pragma unroll
            for (int p = 0; p < 4; p++)
                ldsm4(swaddr(tBf, (uint32_t)(warp_n * 64 + p * 16) + br, kb + bkb), bf[p]);
            #pragma unroll
            for (int mt = 0; mt < 2; mt++)
                #pragma unroll
                for (int p = 0; p < 4; p++) {
                    mma16816h(acc[mt][2 * p],     af[mt], &bf[p][0]);
                    mma16816h(acc[mt][2 * p + 1], af[mt], &bf[p][2]);
                }
        }
    }

    int lm = lane >> 2;
    int lc = (lane & 3) * 2;
    int cm = m0 + warp_m * 32;
    int cn = n0 + warp_n * 64;
    #pragma unroll
    for (int mt = 0; mt < 2; mt++) {
        #pragma unroll
        for (int nt = 0; nt < 8; nt++) {
            int r0 = cm + mt * 16 + lm;
            int cc = cn + nt * 8 + lc;
            float2 bv = *(const float2*)&bias[cc];
            float* a = acc[mt][nt];
            float2 o0 = make_float2(a[0] + bv.x, a[1] + bv.y);
            float2 o1 = make_float2(a[2] + bv.x, a[3] + bv.y);
            size_t off0 = (size_t)r0 * DDIM + cc;
            size_t off1 = (size_t)(r0 + 8) * DDIM + cc;
            if (doAdd == 1) {
                float2 q0 = *(const float2*)(addp + off0);
                float2 q1 = *(const float2*)(addp + off1);
                o0.x += q0.x; o0.y += q0.y;
                o1.x += q1.x; o1.y += q1.y;
            } else if (doAdd == 2) {
                __half2 q0 = *(const __half2*)(addpH + off0);
                __half2 q1 = *(const __half2*)(addpH + off1);
                o0.x += __low2float(q0); o0.y += __high2float(q0);
                o1.x += __low2float(q1); o1.y += __high2float(q1);
            }
            if (C) {
                *(float2*)(C + off0) = o0;
                *(float2*)(C + off1) = o1;
            }
            if (Sf) {
                *(__half2*)(Sf + off0) = __floats2half2_rn(o0.x, o0.y);
                *(__half2*)(Sf + off1) = __floats2half2_rn(o1.x, o1.y);
            }
        }
    }
}

// ---------------- dual-weight fused GEMM -----------------------------------
// mode 0 (COMB): O1 <- fp16( gelu(sigmoid(v1)) * v2 )
// mode 1 (GATE): O1 <- fp16(v1) ; O2 <- fp16( sqrt(1-a^2)*sigmoid(v2)*rg )
#define D_TILE_B 8192

__global__ void __launch_bounds__(256, 2)
fgemm_dual_kernel(const __half* __restrict__ Af,
                  const __half* __restrict__ B1, const __half* __restrict__ B2,
                  const float* __restrict__ bias1, const float* __restrict__ bias2,
                  int mode,
                  __half* __restrict__ O1, __half* __restrict__ O2,
                  const float* __restrict__ Lam, const __half* __restrict__ rgbuf) {
    extern __shared__ __align__(1024) char smem_raw[];
    uint32_t smem0 = smem_to_u32(smem_raw);
    uint32_t tbase = (smem0 + 1023u) & ~1023u;

    int tid = threadIdx.x;
    int wid = tid >> 5;
    int lane = tid & 31;
    int m0 = blockIdx.y * 128;
    int n0 = blockIdx.x * 64;

    int row_base = tid >> 3;        // 0..31
    int col = tid & 7;
    const char* srcb[8];
    uint32_t stsoff[8];
    {
        const char* aB  = (const char*)(Af + (size_t)m0 * DDIM);
        const char* b1B = (const char*)(B1 + (size_t)n0 * DDIM);
        const char* b2B = (const char*)(B2 + (size_t)n0 * DDIM);
        #pragma unroll
        for (int i = 0; i < 4; i++) {
            uint32_t rr = (uint32_t)row_base + 32u * i;
            srcb[i] = aB + (size_t)rr * 2048 + col * 16;
            uint32_t off = rr * 128u + (uint32_t)col * 16u;
            stsoff[i] = off ^ ((off >> 3) & 0x70u);
        }
        #pragma unroll
        for (int i = 4; i < 6; i++) {
            uint32_t rr = (uint32_t)row_base + 32u * (i - 4);
            srcb[i] = b1B + (size_t)rr * 2048 + col * 16;
            uint32_t off = rr * 128u + (uint32_t)col * 16u;
            stsoff[i] = F_TILE_A + (off ^ ((off >> 3) & 0x70u));
        }
        #pragma unroll
        for (int i = 6; i < 8; i++) {
            uint32_t rr = (uint32_t)row_base + 32u * (i - 6);
            srcb[i] = b2B + (size_t)rr * 2048 + col * 16;
            uint32_t off = rr * 128u + (uint32_t)col * 16u;
            stsoff[i] = F_TILE_A + D_TILE_B + (off ^ ((off >> 3) & 0x70u));
        }
    }

    #define D_ISSUE(buf, chunk) do { \
        uint32_t db_ = tbase + (uint32_t)(buf) * F_STAGE; \
        _Pragma("unroll") \
        for (int i_ = 0; i_ < 8; i_++) \
            cpasync16(db_ + stsoff[i_], srcb[i_] + (size_t)(chunk) * 128); \
        CP_COMMIT(); \
    } while (0)

    int warp_m = wid & 3;
    int warp_n = wid >> 2;          // 0..1 (32-col halves)
    uint32_t ar  = (uint32_t)((lane & 7) + ((lane >> 3) & 1) * 8);
    uint32_t akb = (uint32_t)(((lane >> 4) & 1) * 16);
    uint32_t br  = (uint32_t)((lane & 7) + ((lane >> 4) & 1) * 8);
    uint32_t bkb = (uint32_t)(((lane >> 3) & 1) * 16);

    float acc1[2][4][4], acc2[2][4][4];
    #pragma unroll
    for (int i = 0; i < 2; i++)
        #pragma unroll
        for (int j = 0; j < 4; j++)
            #pragma unroll
            for (int q = 0; q < 4; q++) { acc1[i][j][q] = 0.0f; acc2[i][j][q] = 0.0f; }

    D_ISSUE(0, 0);

    for (int c = 0; c < NCHUNK; c++) {
        CP_WAIT(0);
        __syncthreads();
        if (c + 1 < NCHUNK) D_ISSUE((c + 1) & 1, c + 1);

        uint32_t sb = tbase + (uint32_t)(c & 1) * F_STAGE;
        uint32_t tAf = sb;
        uint32_t tB1 = sb + F_TILE_A;
        uint32_t tB2 = sb + F_TILE_A + D_TILE_B;

        #pragma unroll
        for (int k16 = 0; k16 < 4; k16++) {
            uint32_t kb = (uint32_t)k16 * 32u;
            uint32_t af[2][4], bf1[2][4], bf2[2][4];
            #pragma unroll
            for (int mt = 0; mt < 2; mt++)
                ldsm4(swaddr(tAf, (uint32_t)(warp_m * 32 + mt * 16) + ar, kb + akb), af[mt]);
            #pragma unroll
            for (int p = 0; p < 2; p++)
                ldsm4(swaddr(tB1, (uint32_t)(warp_n * 32 + p * 16) + br, kb + bkb), bf1[p]);
            #pragma unroll
            for (int p = 0; p < 2; p++)
                ldsm4(swaddr(tB2, (uint32_t)(warp_n * 32 + p * 16) + br, kb + bkb), bf2[p]);
            #pragma unroll
            for (int mt = 0; mt < 2; mt++)
                #pragma unroll
                for (int p = 0; p < 2; p++) {
                    mma16816h(acc1[mt][2 * p],     af[mt], &bf1[p][0]);
                    mma16816h(acc1[mt][2 * p + 1], af[mt], &bf1[p][2]);
                    mma16816h(acc2[mt][2 * p],     af[mt], &bf2[p][0]);
                    mma16816h(acc2[mt][2 * p + 1], af[mt], &bf2[p][2]);
                }
        }
    }

    int lm = lane >> 2;
    int lc = (lane & 3) * 2;
    int cm = m0 + warp_m * 32;
    int cn = n0 + warp_n * 32;
    #pragma unroll
    for (int mt = 0; mt < 2; mt++) {
        #pragma unroll
        for (int nt = 0; nt < 4; nt++) {
            int r0 = cm + mt * 16 + lm;
            int cc = cn + nt * 8 + lc;
            float2 b1v = *(const float2*)&bias1[cc];
            float2 b2v = *(const float2*)&bias2[cc];
            float* a1 = acc1[mt][nt];
            float* a2 = acc2[mt][nt];
            size_t off0 = (size_t)r0 * DDIM + cc;
            size_t off1 = (size_t)(r0 + 8) * DDIM + cc;
            float v1r0x = a1[0] + b1v.x, v1r0y = a1[1] + b1v.y;
            float v1r1x = a1[2] + b1v.x, v1r1y = a1[3] + b1v.y;
            float v2r0x = a2[0] + b2v.x, v2r0y = a2[1] + b2v.y;
            float v2r1x = a2[2] + b2v.x, v2r1y = a2[3] + b2v.y;
            if (mode == 0) {
                *(__half2*)(O1 + off0) = __floats2half2_rn(
                    gelu_exact(sigmoidf_(v1r0x)) * v2r0x,
                    gelu_exact(sigmoidf_(v1r0y)) * v2r0y);
                *(__half2*)(O1 + off1) = __floats2half2_rn(
                    gelu_exact(sigmoidf_(v1r1x)) * v2r1x,
                    gelu_exact(sigmoidf_(v1r1y)) * v2r1y);
            } else {
                float2 lam = *(const float2*)&Lam[cc];
                float la0 = -log1pf(expf(-lam.x));
                float la1 = -log1pf(expf(-lam.y));
                __half2 rg0 = *(const __half2*)(rgbuf + off0);
                __half2 rg1 = *(const __half2*)(rgbuf + off1);
                float a0 = expf(la0 * sigmoidf_(v1r0x) * 0.125f);
                float a1_ = expf(la1 * sigmoidf_(v1r0y) * 0.125f);
                float a2_ = expf(la0 * sigmoidf_(v1r1x) * 0.125f);
                float a3_ = expf(la1 * sigmoidf_(v1r1y) * 0.125f);
                float g0 = sqrtf(fmaxf(1.0f - a0 * a0, 0.0f)) * sigmoidf_(v2r0x) * __low2float(rg0);
                float g1 = sqrtf(fmaxf(1.0f - a1_ * a1_, 0.0f)) * sigmoidf_(v2r0y) * __high2float(rg0);
                float g2 = sqrtf(fmaxf(1.0f - a2_ * a2_, 0.0f)) * sigmoidf_(v2r1x) * __low2float(rg1);
                float g3 = sqrtf(fmaxf(1.0f - a3_ * a3_, 0.0f)) * sigmoidf_(v2r1y) * __high2float(rg1);
                *(__half2*)(O1 + off0) = __floats2half2_rn(v1r0x, v1r0y);
                *(__half2*)(O1 + off1) = __floats2half2_rn(v1r1x, v1r1y);
                *(__half2*)(O2 + off0) = __floats2half2_rn(g0, g1);
                *(__half2*)(O2 + off1) = __floats2half2_rn(g2, g3);
            }
        }
    }
}

// ---------------- rmsnorm (fp32 in) -> fp16, 4 rows per block --------------
__global__ void rmsnorm_f16_kernel(const float* __restrict__ x,
                                   const float* __restrict__ gw,
                                   __half* __restrict__ Sf) {
    int row0 = blockIdx.x * 4;
    int tid = threadIdx.x;
    float4 v[4];
    #pragma unroll
    for (int j = 0; j < 4; j++)
        v[j] = ((const float4*)(x + (size_t)(row0 + j) * DDIM))[tid];
    float4 g = ((const float4*)gw)[tid];

    float ps[4];
    #pragma unroll
    for (int j = 0; j < 4; j++)
        ps[j] = v[j].x * v[j].x + v[j].y * v[j].y + v[j].z * v[j].z + v[j].w * v[j].w;
    #pragma unroll
    for (int j = 0; j < 4; j++)
        #pragma unroll
        for (int o = 16; o > 0; o >>= 1)
            ps[j] += __shfl_xor_sync(0xffffffffu, ps[j], o);

    __shared__ float sred[4][8];
    if ((tid & 31) == 0)
        #pragma unroll
        for (int j = 0; j < 4; j++) sred[j][tid >> 5] = ps[j];
    __syncthreads();
    float s[4];
    #pragma unroll
    for (int j = 0; j < 4; j++) {
        float total = 0.0f;
        #pragma unroll
        for (int i = 0; i < 8; i++) total += sred[j][i];
        s[j] = 32.0f / fmaxf(sqrtf(total), 1e-12f);
    }
    #pragma unroll
    for (int j = 0; j < 4; j++) {
        float o0 = v[j].x * s[j] * g.x, o1 = v[j].y * s[j] * g.y;
        float o2 = v[j].z * s[j] * g.z, o3 = v[j].w * s[j] * g.w;
        size_t base2 = (size_t)(row0 + j) * (DDIM / 2) + tid * 2;
        ((__half2*)Sf)[base2]     = __floats2half2_rn(o0, o1);
        ((__half2*)Sf)[base2 + 1] = __floats2half2_rn(o2, o3);
    }
}

// ---------------- rmsnorm (fp16 in) -> fp16, 4 rows per block --------------
__global__ void rmsnorm_h_kernel(const __half* __restrict__ x16,
                                 const float* __restrict__ gw,
                                 __half* __restrict__ Sf) {
    int row0 = blockIdx.x * 4;
    int tid = threadIdx.x;
    uint2 v[4];
    #pragma unroll
    for (int j = 0; j < 4; j++)
        v[j] = ((const uint2*)(x16 + (size_t)(row0 + j) * DDIM))[tid];
    float4 g = ((const float4*)gw)[tid];

    float f[4][4];
    float ps[4];
    #pragma unroll
    for (int j = 0; j < 4; j++) {
        f[j][0] = h2lo(v[j].x); f[j][1] = h2hi(v[j].x);
        f[j][2] = h2lo(v[j].y); f[j][3] = h2hi(v[j].y);
        ps[j] = f[j][0] * f[j][0] + f[j][1] * f[j][1]
              + f[j][2] * f[j][2] + f[j][3] * f[j][3];
    }
    #pragma unroll
    for (int j = 0; j < 4; j++)
        #pragma unroll
        for (int o = 16; o > 0; o >>= 1)
            ps[j] += __shfl_xor_sync(0xffffffffu, ps[j], o);

    __shared__ float sred[4][8];
    if ((tid & 31) == 0)
        #pragma unroll
        for (int j = 0; j < 4; j++) sred[j][tid >> 5] = ps[j];
    __syncthreads();
    float s[4];
    #pragma unroll
    for (int j = 0; j < 4; j++) {
        float total = 0.0f;
        #pragma unroll
        for (int i = 0; i < 8; i++) total += sred[j][i];
        s[j] = 32.0f / fmaxf(sqrtf(total), 1e-12f);
    }
    #pragma unroll
    for (int j = 0; j < 4; j++) {
        float o0 = f[j][0] * s[j] * g.x, o1 = f[j][1] * s[j] * g.y;
        float o2 = f[j][2] * s[j] * g.z, o3 = f[j][3] * s[j] * g.w;
        size_t base2 = (size_t)(row0 + j) * (DDIM / 2) + tid * 2;
        ((__half2*)Sf)[base2]     = __floats2half2_rn(o0, o1);
        ((__half2*)Sf)[base2 + 1] = __floats2half2_rn(o2, o3);
    }
}

// ---------------- chunked RG-LRU scan (4 chains/thread, uint2) -------------
__global__ void scan1_kernel(const __half* __restrict__ rt, const __half* __restrict__ gt,
                             const float* __restrict__ Lam,
                             __half* __restrict__ hl,
                             float* __restrict__ Acar, float* __restrict__ Hcar) {
    int i = blockIdx.x * 256 + threadIdx.x;     // 0 .. 65535 (quads x chunks)
    int q = i & 1023;
    int chunk = i >> 10;
    int b = q >> 8;
    int dq = q & 255;
    size_t base4 = (((size_t)b * TLEN + (size_t)chunk * CHLEN) * DDIM) / 4 + dq;
    float la[4];
    {
        float4 lam = *(const float4*)&Lam[4 * dq];
        la[0] = -log1pf(expf(-lam.x)); la[1] = -log1pf(expf(-lam.y));
        la[2] = -log1pf(expf(-lam.z)); la[3] = -log1pf(expf(-lam.w));
    }
    float h[4] = {0, 0, 0, 0}, P[4] = {1, 1, 1, 1};
    const uint2* rt4 = (const uint2*)rt;
    const uint2* gt4 = (const uint2*)gt;
    uint2* hl4 = (uint2*)hl;
    #pragma unroll 4
    for (int t = 0; t < CHLEN; t++) {
        size_t a_ = base4 + (size_t)t * (DDIM / 4);
        uint2 rv = rt4[a_], gv = gt4[a_];
        float rr[4] = {h2lo(rv.x), h2hi(rv.x), h2lo(rv.y), h2hi(rv.y)};
        float gg[4] = {h2lo(gv.x), h2hi(gv.x), h2lo(gv.y), h2hi(gv.y)};
        #pragma unroll
        for (int j = 0; j < 4; j++) {
            float a = expf(la[j] * sigmoidf_(rr[j]) * 0.125f);
            h[j] = fmaf(a, h[j], gg[j]);
            P[j] *= a;
        }
        uint2 ho;
        ho.x = pack2h(h[0], h[1]);
        ho.y = pack2h(h[2], h[3]);
        hl4[a_] = ho;
    }
    int chain = b * DDIM + 4 * dq;
    #pragma unroll
    for (int j = 0; j < 4; j++) {
        Acar[chunk * NCHAIN + chain + j] = P[j];
        Hcar[chunk * NCHAIN + chain + j] = h[j];
    }
}

__global__ void scan2_kernel(const float* __restrict__ Acar, const float* __restrict__ Hcar,
                             float* __restrict__ carry) {
    int chain = blockIdx.x * 256 + threadIdx.x;   // 0..4095
    float h = 0.0f;
    #pragma unroll
    for (int c = 0; c < CHUNKS; c++) {
        int idx = c * NCHAIN + chain;
        carry[idx] = h;
        h = fmaf(Acar[idx], h, Hcar[idx]);
    }
}

__global__ void scan3_kernel(const __half* __restrict__ rt, const __half* __restrict__ hl,
                             const float* __restrict__ carry,
                             const float* __restrict__ Lam,
                             __half* __restrict__ linSf) {
    int i = blockIdx.x * 256 + threadIdx.x;     // 0 .. 65535
    int q = i & 1023;
    int chunk = i >> 10;
    int b = q >> 8;
    int dq = q & 255;
    size_t base4 = (((size_t)b * TLEN + (size_t)chunk * CHLEN) * DDIM) / 4 + dq;
    float la[4];
    {
        float4 lam = *(const float4*)&Lam[4 * dq];
        la[0] = -log1pf(expf(-lam.x)); la[1] = -log1pf(expf(-lam.y));
        la[2] = -log1pf(expf(-lam.z)); la[3] = -log1pf(expf(-lam.w));
    }
    int chain = b * DDIM + 4 * dq;
    float cin[4], P[4] = {1, 1, 1, 1};
    #pragma unroll
    for (int j = 0; j < 4; j++) cin[j] = carry[chunk * NCHAIN + chain + j];
    const uint2* rt4 = (const uint2*)rt;
    const uint2* hl4 = (const uint2*)hl;
    uint2* ls4 = (uint2*)linSf;
    #pragma unroll 4
    for (int t = 0; t < CHLEN; t++) {
        size_t a_ = base4 + (size_t)t * (DDIM / 4);
        uint2 rv = rt4[a_], hv = hl4[a_], lv = ls4[a_];
        float rr[4] = {h2lo(rv.x), h2hi(rv.x), h2lo(rv.y), h2hi(rv.y)};
        float hh[4] = {h2lo(hv.x), h2hi(hv.x), h2lo(hv.y), h2hi(hv.y)};
        float ll[4] = {h2lo(lv.x), h2hi(lv.x), h2lo(lv.y), h2hi(lv.y)};
        float oo[4];
        #pragma unroll
        for (int j = 0; j < 4; j++) {
            float a = expf(la[j] * sigmoidf_(rr[j]) * 0.125f);
            P[j] *= a;
            float h = fmaf(P[j], cin[j], hh[j]);
            oo[j] = gelu_exact(ll[j]) * h;
        }
        uint2 o;
        o.x = pack2h(oo[0], oo[1]);
        o.y = pack2h(oo[2], oo[3]);
        ls4[a_] = o;
    }
}

// ---------------- launch ---------------------------------------------------
extern "C" void kernel_launch(void* const* d_in, const int* in_sizes, int n_in,
                              void* d_out, int out_size) {
    const float* x      = (const float*)d_in[0];
    const float* g1     = (const float*)d_in[1];
    const float* g2     = (const float*)d_in[2];
    const float* W_lin  = (const float*)d_in[3];
    const float* b_lin  = (const float*)d_in[4];
    const float* W_conv = (const float*)d_in[5];
    const float* b_conv = (const float*)d_in[6];
    const float* W_lin2 = (const float*)d_in[7];
    const float* b_lin2 = (const float*)d_in[8];
    const float* Wa     = (const float*)d_in[9];
    const float* ba     = (const float*)d_in[10];
    const float* Wx     = (const float*)d_in[11];
    const float* bx     = (const float*)d_in[12];
    const float* Lam    = (const float*)d_in[13];
    const float* W1     = (const float*)d_in[14];
    const float* b1     = (const float*)d_in[15];
    const float* W2     = (const float*)d_in[16];
    const float* b2     = (const float*)d_in[17];
    const float* W3     = (const float*)d_in[18];
    const float* b3     = (const float*)d_in[19];
    float* out = (float*)d_out;

    float *Acar, *Hcar, *carry;
    __half *res16, *hl, *Af, *Af2, *rt16, *g16, *Wf;
    cudaGetSymbolAddress((void**)&res16, g_res16);
    cudaGetSymbolAddress((void**)&hl,  g_hl);
    cudaGetSymbolAddress((void**)&Acar, g_Acar);
    cudaGetSymbolAddress((void**)&Hcar, g_Hcar);
    cudaGetSymbolAddress((void**)&carry, g_carry);
    cudaGetSymbolAddress((void**)&Af,   g_Af);
    cudaGetSymbolAddress((void**)&Af2,  g_Af2);
    cudaGetSymbolAddress((void**)&rt16, g_rt16);
    cudaGetSymbolAddress((void**)&g16,  g_g16);
    cudaGetSymbolAddress((void**)&Wf,   g_Wf);

    const int FGEMM_SMEM = 2 * F_STAGE + 1024;   // 66560
    cudaFuncSetAttribute(fgemm_kernel,
                         cudaFuncAttributeMaxDynamicSharedMemorySize, FGEMM_SMEM);
    cudaFuncSetAttribute(fgemm_dual_kernel,
                         cudaFuncAttributeMaxDynamicSharedMemorySize, FGEMM_SMEM);

    dim3 gg1(DDIM / 128, MROWS / 128);       // (8, 128)   singles
    dim3 ggd(DDIM / 64, MROWS / 128);        // (16, 128)  duals
    dim3 cw(DDIM * DDIM / 4 / 512, 8);       // (512, 8)   all weights
    int scBlocks  = (NCHAIN / 4 * CHUNKS) / 256;      // 256
    const size_t WN = (size_t)DDIM * DDIM;

    const float* FZ = (const float*)nullptr;
    float* FZo = (float*)nullptr;
    __half* HZ = (__half*)nullptr;
    const __half* HZc = (const __half*)nullptr;

    // 0) convert all 8 weights: 0:W_lin 1:W_conv 2:Wa 3:Wx 4:W_lin2 5:W1 6:W2 7:W3
    conv_all_w_kernel<<<cw, 256>>>(W_lin, W_conv, Wa, Wx, W_lin2, W1, W2, W3, Wf);
    // 1) Af = fp16(rmsnorm(x, g1))
    rmsnorm_f16_kernel<<<MROWS / 4, 256>>>(x, g1, Af);
    // 2) lin(fp16 Af2) = xn @ W_lin^T + b_lin
    fgemm_kernel<<<gg1, 256, FGEMM_SMEM>>>(Af, Wf, b_lin, FZ, HZc, FZo, 0, Af2);
    // 3) rg(fp16 Af) = lin @ W_conv^T + b_conv
    fgemm_kernel<<<gg1, 256, FGEMM_SMEM>>>(Af2, Wf + WN, b_conv, FZ, HZc, FZo, 0, Af);
    // 4) dual GATE: rt16 = rg@Wa^T+ba (pre-act) ; g16 = sqrt(1-a^2)*sig(rg@Wx^T+bx)*rg
    fgemm_dual_kernel<<<ggd, 256, FGEMM_SMEM>>>(Af, Wf + 2 * WN, Wf + 3 * WN,
                                                ba, bx, 1, rt16, g16, Lam, Af);
    // 5-7) chunked scan
    scan1_kernel<<<scBlocks, 256>>>(rt16, g16, Lam, hl, Acar, Hcar);
    scan2_kernel<<<NCHAIN / 256, 256>>>(Acar, Hcar, carry);
    scan3_kernel<<<scBlocks, 256>>>(rt16, hl, carry, Lam, Af2);
    // 8) res16 = fp16( (gelu(lin)*h) @ W_lin2^T + b_lin2 + x )   (slot 4)
    fgemm_kernel<<<gg1, 256, FGEMM_SMEM>>>(Af2, Wf + 4 * WN, b_lin2, x, HZc, FZo, 1, res16);
    // 9) Af = fp16(rmsnorm(res16, g2))
    rmsnorm_h_kernel<<<MROWS / 4, 256>>>(res16, g2, Af);
    // 10) dual COMB: Af2 = gelu(sig(xm@W1^T+b1)) * (xm@W2^T+b2)   (slots 5,6)
    fgemm_dual_kernel<<<ggd, 256, FGEMM_SMEM>>>(Af, Wf + 5 * WN, Wf + 6 * WN,
                                                b1, b2, 0, Af2, HZ, FZ, HZc);
    // 12) out = combined @ W3^T + b3 + res16   (slot 7)
    fgemm_kernel<<<gg1, 256, FGEMM_SMEM>>>(Af2, Wf + 7 * WN, b3, FZ, res16, out, 2, HZ);

    (void)in_sizes; (void)n_in; (void)out_size;
}

// round 16
// speedup vs baseline: 1.1412x; 1.0202x over previous
#include <cuda_runtime.h>
#include <cuda_fp16.h>
#include <math.h>
#include <cstdint>

// Problem dims
#define MROWS 16384   // B*T = 4*4096
#define DDIM  1024
#define TLEN  4096
#define CHUNKS 64
#define CHLEN  (TLEN / CHUNKS)   // 64
#define NCHAIN 4096              // B * D

// ---------------- scratch (device globals; no allocation allowed) ----------
__device__ __half g_res16[MROWS * DDIM];
__device__ __half g_Af  [MROWS * DDIM];
__device__ __half g_Af2 [MROWS * DDIM];
__device__ __half g_rt16[MROWS * DDIM];
__device__ __half g_g16 [MROWS * DDIM];
__device__ __half g_Wf [8 * DDIM * DDIM];   // 8 weight slots
__device__ float g_Acar[NCHAIN * CHUNKS];
__device__ float g_Hcar[NCHAIN * CHUNKS];
__device__ float g_carry[NCHAIN * CHUNKS];

// ---------------- base-ISA tensor helpers ----------------------------------
__device__ __forceinline__ uint32_t smem_to_u32(const void* p) {
    uint32_t a;
    asm("{ .reg .u64 t; cvta.to.shared.u64 t, %1; cvt.u32.u64 %0, t; }"
        : "=r"(a) : "l"(p));
    return a;
}
__device__ __forceinline__ void cpasync16(uint32_t dst, const void* src) {
    asm volatile("cp.async.cg.shared.global [%0], [%1], 16;"
                 :: "r"(dst), "l"(src) : "memory");
}
#define CP_COMMIT() asm volatile("cp.async.commit_group;" ::: "memory")
#define CP_WAIT(n)  asm volatile("cp.async.wait_group %0;" :: "n"(n) : "memory")

__device__ __forceinline__ void ldsm4(uint32_t addr, uint32_t* r) {
    asm volatile("ldmatrix.sync.aligned.m8n8.x4.shared.b16 {%0,%1,%2,%3}, [%4];"
                 : "=r"(r[0]), "=r"(r[1]), "=r"(r[2]), "=r"(r[3]) : "r"(addr));
}
__device__ __forceinline__ void mma16816h(float* c, const uint32_t* a, const uint32_t* b) {
    asm volatile(
        "mma.sync.aligned.m16n8k16.row.col.f32.f16.f16.f32 "
        "{%0,%1,%2,%3}, {%4,%5,%6,%7}, {%8,%9}, {%0,%1,%2,%3};"
        : "+f"(c[0]), "+f"(c[1]), "+f"(c[2]), "+f"(c[3])
        : "r"(a[0]), "r"(a[1]), "r"(a[2]), "r"(a[3]), "r"(b[0]), "r"(b[1]));
}

// ---------------- math helpers ---------------------------------------------
__device__ __forceinline__ float gelu_exact(float x) {
    return 0.5f * x * (1.0f + erff(x * 0.70710678118654752440f));
}
__device__ __forceinline__ float sigmoidf_(float x) {
    return 1.0f / (1.0f + expf(-x));
}
__device__ __forceinline__ float h2lo(uint32_t u) {
    __half2 h = *(__half2*)&u;
    return __low2float(h);
}
__device__ __forceinline__ float h2hi(uint32_t u) {
    __half2 h = *(__half2*)&u;
    return __high2float(h);
}
__device__ __forceinline__ uint32_t pack2h(float a, float b) {
    __half2 h = __floats2half2_rn(a, b);
    return *(uint32_t*)&h;
}

// ---------------- prologue: rmsnorm(x,g1) + convert all 8 weights ----------
// grid.x = 8192: blocks [0,4096) do rmsnorm (4 rows each),
// blocks [4096,8192) convert weights (slot = (bx-4096)>>9, 512 blocks/slot).
__global__ void prologue_kernel(const float* __restrict__ x, const float* __restrict__ g1,
                                __half* __restrict__ Af,
                                const float* __restrict__ w0, const float* __restrict__ w1,
                                const float* __restrict__ w2, const float* __restrict__ w3,
                                const float* __restrict__ w4, const float* __restrict__ w5,
                                const float* __restrict__ w6, const float* __restrict__ w7,
                                __half* __restrict__ Wf) {
    int bx = blockIdx.x;
    int tid = threadIdx.x;
    if (bx < 4096) {
        // rmsnorm, 4 rows per block
        int row0 = bx * 4;
        float4 v[4];
        #pragma unroll
        for (int j = 0; j < 4; j++)
            v[j] = ((const float4*)(x + (size_t)(row0 + j) * DDIM))[tid];
        float4 g = ((const float4*)g1)[tid];
        float ps[4];
        #pragma unroll
        for (int j = 0; j < 4; j++)
            ps[j] = v[j].x * v[j].x + v[j].y * v[j].y + v[j].z * v[j].z + v[j].w * v[j].w;
        #pragma unroll
        for (int j = 0; j < 4; j++)
            #pragma unroll
            for (int o = 16; o > 0; o >>= 1)
                ps[j] += __shfl_xor_sync(0xffffffffu, ps[j], o);
        __shared__ float sred[4][8];
        if ((tid & 31) == 0)
            #pragma unroll
            for (int j = 0; j < 4; j++) sred[j][tid >> 5] = ps[j];
        __syncthreads();
        float s[4];
        #pragma unroll
        for (int j = 0; j < 4; j++) {
            float total = 0.0f;
            #pragma unroll
            for (int i = 0; i < 8; i++) total += sred[j][i];
            s[j] = 32.0f / fmaxf(sqrtf(total), 1e-12f);
        }
        #pragma unroll
        for (int j = 0; j < 4; j++) {
            float o0 = v[j].x * s[j] * g.x, o1 = v[j].y * s[j] * g.y;
            float o2 = v[j].z * s[j] * g.z, o3 = v[j].w * s[j] * g.w;
            size_t base2 = (size_t)(row0 + j) * (DDIM / 2) + tid * 2;
            ((__half2*)Af)[base2]     = __floats2half2_rn(o0, o1);
            ((__half2*)Af)[base2 + 1] = __floats2half2_rn(o2, o3);
        }
    } else {
        // weight conversion
        const float* srcs[8] = {w0, w1, w2, w3, w4, w5, w6, w7};
        int bxr = bx - 4096;
        int slot = bxr >> 9;
        const float* src = srcs[slot];
        __half* d = Wf + (size_t)slot * DDIM * DDIM;
        int i = ((bxr & 511) * 256 + tid) * 2;
        float4 v0 = ((const float4*)src)[i];
        float4 v1 = ((const float4*)src)[i + 1];
        ((__half2*)d)[2 * i]     = __floats2half2_rn(v0.x, v0.y);
        ((__half2*)d)[2 * i + 1] = __floats2half2_rn(v0.z, v0.w);
        ((__half2*)d)[2 * i + 2] = __floats2half2_rn(v1.x, v1.y);
        ((__half2*)d)[2 * i + 3] = __floats2half2_rn(v1.z, v1.w);
    }
}

// ---------------- fp16 1-term mma.sync GEMM, BN=128, 2-stage ---------------
// doAdd: 0 = none, 1 = += addp (fp32), 2 = += addpH (fp16)
#define F_TILE_A 16384               // 128 x 64 fp16
#define F_TILE_B 16384               // 128 x 64 fp16
#define F_STAGE  32768
#define NCHUNK (DDIM / 64)           // 16

__device__ __forceinline__ uint32_t swaddr(uint32_t tile, uint32_t row, uint32_t kb) {
    uint32_t off = row * 128u + kb;
    return tile + (off ^ ((off >> 3) & 0x70u));
}

__global__ void __launch_bounds__(256, 2)
fgemm_kernel(const __half* __restrict__ Af, const __half* __restrict__ Bf,
             const float* __restrict__ bias,
             const float* __restrict__ addp, const __half* __restrict__ addpH,
             float* __restrict__ C, int doAdd,
             __half* __restrict__ Sf) {
    extern __shared__ __align__(1024) char smem_raw[];
    uint32_t smem0 = smem_to_u32(smem_raw);
    uint32_t tbase = (smem0 + 1023u) & ~1023u;

    int tid = threadIdx.x;
    int wid = tid >> 5;
    int lane = tid & 31;
    int m0 = blockIdx.y * 128;
    int n0 = blockIdx.x * 128;

    int row_base = tid >> 3;        // 0..31
    int col = tid & 7;
    const char* srcb[8];
    uint32_t stsoff[8];
    {
        const char* aB = (const char*)(Af + (size_t)m0 * DDIM);
        const char* bB = (const char*)(Bf + (size_t)n0 * DDIM);
        #pragma unroll
        for (int i = 0; i < 4; i++) {
            uint32_t rr = (uint32_t)row_base + 32u * i;
            srcb[i] = aB + (size_t)rr * 2048 + col * 16;
            uint32_t off = rr * 128u + (uint32_t)col * 16u;
            stsoff[i] = off ^ ((off >> 3) & 0x70u);
        }
        #pragma unroll
        for (int i = 4; i < 8; i++) {
            uint32_t rr = (uint32_t)row_base + 32u * (i - 4);
            srcb[i] = bB + (size_t)rr * 2048 + col * 16;
            uint32_t off = rr * 128u + (uint32_t)col * 16u;
            stsoff[i] = F_TILE_A + (off ^ ((off >> 3) & 0x70u));
        }
    }

    #define F_ISSUE(buf, chunk) do { \
        uint32_t db_ = tbase + (uint32_t)(buf) * F_STAGE; \
        _Pragma("unroll") \
        for (int i_ = 0; i_ < 8; i_++) \
            cpasync16(db_ + stsoff[i_], srcb[i_] + (size_t)(chunk) * 128); \
        CP_COMMIT(); \
    } while (0)

    int warp_m = wid & 3;
    int warp_n = wid >> 2;          // 0..1
    uint32_t ar  = (uint32_t)((lane & 7) + ((lane >> 3) & 1) * 8);
    uint32_t akb = (uint32_t)(((lane >> 4) & 1) * 16);
    uint32_t br  = (uint32_t)((lane & 7) + ((lane >> 4) & 1) * 8);
    uint32_t bkb = (uint32_t)(((lane >> 3) & 1) * 16);

    float acc[2][8][4];
    #pragma unroll
    for (int i = 0; i < 2; i++)
        #pragma unroll
        for (int j = 0; j < 8; j++)
            #pragma unroll
            for (int q = 0; q < 4; q++) acc[i][j][q] = 0.0f;

    F_ISSUE(0, 0);

    for (int c = 0; c < NCHUNK; c++) {
        CP_WAIT(0);
        __syncthreads();
        if (c + 1 < NCHUNK) F_ISSUE((c + 1) & 1, c + 1);

        uint32_t sb = tbase + (uint32_t)(c & 1) * F_STAGE;
        uint32_t tAf = sb;
        uint32_t tBf = sb + F_TILE_A;

        #pragma unroll
        for (int k16 = 0; k16 < 4; k16++) {
            uint32_t kb = (uint32_t)k16 * 32u;
            uint32_t af[2][4], bf[4][4];
            #pragma unroll
            for (int mt = 0; mt < 2; mt++)
                ldsm4(swaddr(tAf, (uint32_t)(warp_m * 32 + mt * 16) + ar, kb + akb), af[mt]);
            #pragma unroll
            for (int p = 0; p < 4; p++)
                ldsm4(swaddr(tBf, (uint32_t)(warp_n * 64 + p * 16) + br, kb + bkb), bf[p]);
            #pragma unroll
            for (int mt = 0; mt < 2; mt++)
                #pragma unroll
                for (int p = 0; p < 4; p++) {
                    mma16816h(acc[mt][2 * p],     af[mt], &bf[p][0]);
                    mma16816h(acc[mt][2 * p + 1], af[mt], &bf[p][2]);
                }
        }
    }

    int lm = lane >> 2;
    int lc = (lane & 3) * 2;
    int cm = m0 + warp_m * 32;
    int cn = n0 + warp_n * 64;
    #pragma unroll
    for (int mt = 0; mt < 2; mt++) {
        #pragma unroll
        for (int nt = 0; nt < 8; nt++) {
            int r0 = cm + mt * 16 + lm;
            int cc = cn + nt * 8 + lc;
            float2 bv = *(const float2*)&bias[cc];
            float* a = acc[mt][nt];
            float2 o0 = make_float2(a[0] + bv.x, a[1] + bv.y);
            float2 o1 = make_float2(a[2] + bv.x, a[3] + bv.y);
            size_t off0 = (size_t)r0 * DDIM + cc;
            size_t off1 = (size_t)(r0 + 8) * DDIM + cc;
            if (doAdd == 1) {
                float2 q0 = *(const float2*)(addp + off0);
                float2 q1 = *(const float2*)(addp + off1);
                o0.x += q0.x; o0.y += q0.y;
                o1.x += q1.x; o1.y += q1.y;
            } else if (doAdd == 2) {
                __half2 q0 = *(const __half2*)(addpH + off0);
                __half2 q1 = *(const __half2*)(addpH + off1);
                o0.x += __low2float(q0); o0.y += __high2float(q0);
                o1.x += __low2float(q1); o1.y += __high2float(q1);
            }
            if (C) {
                *(float2*)(C + off0) = o0;
                *(float2*)(C + off1) = o1;
            }
            if (Sf) {
                *(__half2*)(Sf + off0) = __floats2half2_rn(o0.x, o0.y);
                *(__half2*)(Sf + off1) = __floats2half2_rn(o1.x, o1.y);
            }
        }
    }
}

// ---------------- dual-weight fused GEMM -----------------------------------
// mode 0 (COMB): O1 <- fp16( gelu(sigmoid(v1)) * v2 )
// mode 1 (GATE): O1 <- fp16(v1) ; O2 <- fp16( sqrt(1-a^2)*sigmoid(v2)*rg )
#define D_TILE_B 8192

__global__ void __launch_bounds__(256, 2)
fgemm_dual_kernel(const __half* __restrict__ Af,
                  const __half* __restrict__ B1, const __half* __restrict__ B2,
                  const float* __restrict__ bias1, const float* __restrict__ bias2,
                  int mode,
                  __half* __restrict__ O1, __half* __restrict__ O2,
                  const float* __restrict__ Lam, const __half* __restrict__ rgbuf) {
    extern __shared__ __align__(1024) char smem_raw[];
    uint32_t smem0 = smem_to_u32(smem_raw);
    uint32_t tbase = (smem0 + 1023u) & ~1023u;

    int tid = threadIdx.x;
    int wid = tid >> 5;
    int lane = tid & 31;
    int m0 = blockIdx.y * 128;
    int n0 = blockIdx.x * 64;

    int row_base = tid >> 3;        // 0..31
    int col = tid & 7;
    const char* srcb[8];
    uint32_t stsoff[8];
    {
        const char* aB  = (const char*)(Af + (size_t)m0 * DDIM);
        const char* b1B = (const char*)(B1 + (size_t)n0 * DDIM);
        const char* b2B = (const char*)(B2 + (size_t)n0 * DDIM);
        #pragma unroll
        for (int i = 0; i < 4; i++) {
            uint32_t rr = (uint32_t)row_base + 32u * i;
            srcb[i] = aB + (size_t)rr * 2048 + col * 16;
            uint32_t off = rr * 128u + (uint32_t)col * 16u;
            stsoff[i] = off ^ ((off >> 3) & 0x70u);
        }
        #pragma unroll
        for (int i = 4; i < 6; i++) {
            uint32_t rr = (uint32_t)row_base + 32u * (i - 4);
            srcb[i] = b1B + (size_t)rr * 2048 + col * 16;
            uint32_t off = rr * 128u + (uint32_t)col * 16u;
            stsoff[i] = F_TILE_A + (off ^ ((off >> 3) & 0x70u));
        }
        #pragma unroll
        for (int i = 6; i < 8; i++) {
            uint32_t rr = (uint32_t)row_base + 32u * (i - 6);
            srcb[i] = b2B + (size_t)rr * 2048 + col * 16;
            uint32_t off = rr * 128u + (uint32_t)col * 16u;
            stsoff[i] = F_TILE_A + D_TILE_B + (off ^ ((off >> 3) & 0x70u));
        }
    }

    #define D_ISSUE(buf, chunk) do { \
        uint32_t db_ = tbase + (uint32_t)(buf) * F_STAGE; \
        _Pragma("unroll") \
        for (int i_ = 0; i_ < 8; i_++) \
            cpasync16(db_ + stsoff[i_], srcb[i_] + (size_t)(chunk) * 128); \
        CP_COMMIT(); \
    } while (0)

    int warp_m = wid & 3;
    int warp_n = wid >> 2;          // 0..1 (32-col halves)
    uint32_t ar  = (uint32_t)((lane & 7) + ((lane >> 3) & 1) * 8);
    uint32_t akb = (uint32_t)(((lane >> 4) & 1) * 16);
    uint32_t br  = (uint32_t)((lane & 7) + ((lane >> 4) & 1) * 8);
    uint32_t bkb = (uint32_t)(((lane >> 3) & 1) * 16);

    float acc1[2][4][4], acc2[2][4][4];
    #pragma unroll
    for (int i = 0; i < 2; i++)
        #pragma unroll
        for (int j = 0; j < 4; j++)
            #pragma unroll
            for (int q = 0; q < 4; q++) { acc1[i][j][q] = 0.0f; acc2[i][j][q] = 0.0f; }

    D_ISSUE(0, 0);

    for (int c = 0; c < NCHUNK; c++) {
        CP_WAIT(0);
        __syncthreads();
        if (c + 1 < NCHUNK) D_ISSUE((c + 1) & 1, c + 1);

        uint32_t sb = tbase + (uint32_t)(c & 1) * F_STAGE;
        uint32_t tAf = sb;
        uint32_t tB1 = sb + F_TILE_A;
        uint32_t tB2 = sb + F_TILE_A + D_TILE_B;

        #pragma unroll
        for (int k16 = 0; k16 < 4; k16++) {
            uint32_t kb = (uint32_t)k16 * 32u;
            uint32_t af[2][4], bf1[2][4], bf2[2][4];
            #pragma unroll
            for (int mt = 0; mt < 2; mt++)
                ldsm4(swaddr(tAf, (uint32_t)(warp_m * 32 + mt * 16) + ar, kb + akb), af[mt]);
            #pragma unroll
            for (int p = 0; p < 2; p++)
                ldsm4(swaddr(tB1, (uint32_t)(warp_n * 32 + p * 16) + br, kb + bkb), bf1[p]);
            #pragma unroll
            for (int p = 0; p < 2; p++)
                ldsm4(swaddr(tB2, (uint32_t)(warp_n * 32 + p * 16) + br, kb + bkb), bf2[p]);
            #pragma unroll
            for (int mt = 0; mt < 2; mt++)
                #pragma unroll
                for (int p = 0; p < 2; p++) {
                    mma16816h(acc1[mt][2 * p],     af[mt], &bf1[p][0]);
                    mma16816h(acc1[mt][2 * p + 1], af[mt], &bf1[p][2]);
                    mma16816h(acc2[mt][2 * p],     af[mt], &bf2[p][0]);
                    mma16816h(acc2[mt][2 * p + 1], af[mt], &bf2[p][2]);
                }
        }
    }

    int lm = lane >> 2;
    int lc = (lane & 3) * 2;
    int cm = m0 + warp_m * 32;
    int cn = n0 + warp_n * 32;
    #pragma unroll
    for (int mt = 0; mt < 2; mt++) {
        #pragma unroll
        for (int nt = 0; nt < 4; nt++) {
            int r0 = cm + mt * 16 + lm;
            int cc = cn + nt * 8 + lc;
            float2 b1v = *(const float2*)&bias1[cc];
            float2 b2v = *(const float2*)&bias2[cc];
            float* a1 = acc1[mt][nt];
            float* a2 = acc2[mt][nt];
            size_t off0 = (size_t)r0 * DDIM + cc;
            size_t off1 = (size_t)(r0 + 8) * DDIM + cc;
            float v1r0x = a1[0] + b1v.x, v1r0y = a1[1] + b1v.y;
            float v1r1x = a1[2] + b1v.x, v1r1y = a1[3] + b1v.y;
            float v2r0x = a2[0] + b2v.x, v2r0y = a2[1] + b2v.y;
            float v2r1x = a2[2] + b2v.x, v2r1y = a2[3] + b2v.y;
            if (mode == 0) {
                *(__half2*)(O1 + off0) = __floats2half2_rn(
                    gelu_exact(sigmoidf_(v1r0x)) * v2r0x,
                    gelu_exact(sigmoidf_(v1r0y)) * v2r0y);
                *(__half2*)(O1 + off1) = __floats2half2_rn(
                    gelu_exact(sigmoidf_(v1r1x)) * v2r1x,
                    gelu_exact(sigmoidf_(v1r1y)) * v2r1y);
            } else {
                float2 lam = *(const float2*)&Lam[cc];
                float la0 = -log1pf(expf(-lam.x));
                float la1 = -log1pf(expf(-lam.y));
                __half2 rg0 = *(const __half2*)(rgbuf + off0);
                __half2 rg1 = *(const __half2*)(rgbuf + off1);
                float a0 = expf(la0 * sigmoidf_(v1r0x) * 0.125f);
                float a1_ = expf(la1 * sigmoidf_(v1r0y) * 0.125f);
                float a2_ = expf(la0 * sigmoidf_(v1r1x) * 0.125f);
                float a3_ = expf(la1 * sigmoidf_(v1r1y) * 0.125f);
                float g0 = sqrtf(fmaxf(1.0f - a0 * a0, 0.0f)) * sigmoidf_(v2r0x) * __low2float(rg0);
                float g1 = sqrtf(fmaxf(1.0f - a1_ * a1_, 0.0f)) * sigmoidf_(v2r0y) * __high2float(rg0);
                float g2 = sqrtf(fmaxf(1.0f - a2_ * a2_, 0.0f)) * sigmoidf_(v2r1x) * __low2float(rg1);
                float g3 = sqrtf(fmaxf(1.0f - a3_ * a3_, 0.0f)) * sigmoidf_(v2r1y) * __high2float(rg1);
                *(__half2*)(O1 + off0) = __floats2half2_rn(v1r0x, v1r0y);
                *(__half2*)(O1 + off1) = __floats2half2_rn(v1r1x, v1r1y);
                *(__half2*)(O2 + off0) = __floats2half2_rn(g0, g1);
                *(__half2*)(O2 + off1) = __floats2half2_rn(g2, g3);
            }
        }
    }
}

// ---------------- rmsnorm (fp16 in) -> fp16, 4 rows per block --------------
__global__ void rmsnorm_h_kernel(const __half* __restrict__ x16,
                                 const float* __restrict__ gw,
                                 __half* __restrict__ Sf) {
    int row0 = blockIdx.x * 4;
    int tid = threadIdx.x;
    uint2 v[4];
    #pragma unroll
    for (int j = 0; j < 4; j++)
        v[j] = ((const uint2*)(x16 + (size_t)(row0 + j) * DDIM))[tid];
    float4 g = ((const float4*)gw)[tid];

    float f[4][4];
    float ps[4];
    #pragma unroll
    for (int j = 0; j < 4; j++) {
        f[j][0] = h2lo(v[j].x); f[j][1] = h2hi(v[j].x);
        f[j][2] = h2lo(v[j].y); f[j][3] = h2hi(v[j].y);
        ps[j] = f[j][0] * f[j][0] + f[j][1] * f[j][1]
              + f[j][2] * f[j][2] + f[j][3] * f[j][3];
    }
    #pragma unroll
    for (int j = 0; j < 4; j++)
        #pragma unroll
        for (int o = 16; o > 0; o >>= 1)
            ps[j] += __shfl_xor_sync(0xffffffffu, ps[j], o);

    __shared__ float sred[4][8];
    if ((tid & 31) == 0)
        #pragma unroll
        for (int j = 0; j < 4; j++) sred[j][tid >> 5] = ps[j];
    __syncthreads();
    float s[4];
    #pragma unroll
    for (int j = 0; j < 4; j++) {
        float total = 0.0f;
        #pragma unroll
        for (int i = 0; i < 8; i++) total += sred[j][i];
        s[j] = 32.0f / fmaxf(sqrtf(total), 1e-12f);
    }
    #pragma unroll
    for (int j = 0; j < 4; j++) {
        float o0 = f[j][0] * s[j] * g.x, o1 = f[j][1] * s[j] * g.y;
        float o2 = f[j][2] * s[j] * g.z, o3 = f[j][3] * s[j] * g.w;
        size_t base2 = (size_t)(row0 + j) * (DDIM / 2) + tid * 2;
        ((__half2*)Sf)[base2]     = __floats2half2_rn(o0, o1);
        ((__half2*)Sf)[base2 + 1] = __floats2half2_rn(o2, o3);
    }
}

// ---------------- chunked RG-LRU scan (4 chains/thread, uint2) -------------
// pass 1: chunk aggregates only (no hl store)
__global__ void scan1_kernel(const __half* __restrict__ rt, const __half* __restrict__ gt,
                             const float* __restrict__ Lam,
                             float* __restrict__ Acar, float* __restrict__ Hcar) {
    int i = blockIdx.x * 256 + threadIdx.x;     // 0 .. 65535 (quads x chunks)
    int q = i & 1023;
    int chunk = i >> 10;
    int b = q >> 8;
    int dq = q & 255;
    size_t base4 = (((size_t)b * TLEN + (size_t)chunk * CHLEN) * DDIM) / 4 + dq;
    float la[4];
    {
        float4 lam = *(const float4*)&Lam[4 * dq];
        la[0] = -log1pf(expf(-lam.x)); la[1] = -log1pf(expf(-lam.y));
        la[2] = -log1pf(expf(-lam.z)); la[3] = -log1pf(expf(-lam.w));
    }
    float h[4] = {0, 0, 0, 0}, P[4] = {1, 1, 1, 1};
    const uint2* rt4 = (const uint2*)rt;
    const uint2* gt4 = (const uint2*)gt;
    #pragma unroll 4
    for (int t = 0; t < CHLEN; t++) {
        size_t a_ = base4 + (size_t)t * (DDIM / 4);
        uint2 rv = rt4[a_], gv = gt4[a_];
        float rr[4] = {h2lo(rv.x), h2hi(rv.x), h2lo(rv.y), h2hi(rv.y)};
        float gg[4] = {h2lo(gv.x), h2hi(gv.x), h2lo(gv.y), h2hi(gv.y)};
        #pragma unroll
        for (int j = 0; j < 4; j++) {
            float a = expf(la[j] * sigmoidf_(rr[j]) * 0.125f);
            h[j] = fmaf(a, h[j], gg[j]);
            P[j] *= a;
        }
    }
    int chain = b * DDIM + 4 * dq;
    #pragma unroll
    for (int j = 0; j < 4; j++) {
        Acar[chunk * NCHAIN + chain + j] = P[j];
        Hcar[chunk * NCHAIN + chain + j] = h[j];
    }
}

// pass 2: serial scan over chunk aggregates (per chain)
__global__ void scan2_kernel(const float* __restrict__ Acar, const float* __restrict__ Hcar,
                             float* __restrict__ carry) {
    int chain = blockIdx.x * 256 + threadIdx.x;   // 0..4095
    float h = 0.0f;
    #pragma unroll
    for (int c = 0; c < CHUNKS; c++) {
        int idx = c * NCHAIN + chain;
        carry[idx] = h;
        h = fmaf(Acar[idx], h, Hcar[idx]);
    }
}

// pass 3: recompute local scan + carry, fused gelu(lin)*h, fp16 in-place
__global__ void scan3_kernel(const __half* __restrict__ rt, const __half* __restrict__ gt,
                             const float* __restrict__ carry,
                             const float* __restrict__ Lam,
                             __half* __restrict__ linSf) {
    int i = blockIdx.x * 256 + threadIdx.x;     // 0 .. 65535
    int q = i & 1023;
    int chunk = i >> 10;
    int b = q >> 8;
    int dq = q & 255;
    size_t base4 = (((size_t)b * TLEN + (size_t)chunk * CHLEN) * DDIM) / 4 + dq;
    float la[4];
    {
        float4 lam = *(const float4*)&Lam[4 * dq];
        la[0] = -log1pf(expf(-lam.x)); la[1] = -log1pf(expf(-lam.y));
        la[2] = -log1pf(expf(-lam.z)); la[3] = -log1pf(expf(-lam.w));
    }
    int chain = b * DDIM + 4 * dq;
    float cin[4], P[4] = {1, 1, 1, 1}, hloc[4] = {0, 0, 0, 0};
    #pragma unroll
    for (int j = 0; j < 4; j++) cin[j] = carry[chunk * NCHAIN + chain + j];
    const uint2* rt4 = (const uint2*)rt;
    const uint2* gt4 = (const uint2*)gt;
    uint2* ls4 = (uint2*)linSf;
    #pragma unroll 4
    for (int t = 0; t < CHLEN; t++) {
        size_t a_ = base4 + (size_t)t * (DDIM / 4);
        uint2 rv = rt4[a_], gv = gt4[a_], lv = ls4[a_];
        float rr[4] = {h2lo(rv.x), h2hi(rv.x), h2lo(rv.y), h2hi(rv.y)};
        float gg[4] = {h2lo(gv.x), h2hi(gv.x), h2lo(gv.y), h2hi(gv.y)};
        float ll[4] = {h2lo(lv.x), h2hi(lv.x), h2lo(lv.y), h2hi(lv.y)};
        float oo[4];
        #pragma unroll
        for (int j = 0; j < 4; j++) {
            float a = expf(la[j] * sigmoidf_(rr[j]) * 0.125f);
            hloc[j] = fmaf(a, hloc[j], gg[j]);
            P[j] *= a;
            float h = fmaf(P[j], cin[j], hloc[j]);
            oo[j] = gelu_exact(ll[j]) * h;
        }
        uint2 o;
        o.x = pack2h(oo[0], oo[1]);
        o.y = pack2h(oo[2], oo[3]);
        ls4[a_] = o;
    }
}

// ---------------- launch ---------------------------------------------------
extern "C" void kernel_launch(void* const* d_in, const int* in_sizes, int n_in,
                              void* d_out, int out_size) {
    const float* x      = (const float*)d_in[0];
    const float* g1     = (const float*)d_in[1];
    const float* g2     = (const float*)d_in[2];
    const float* W_lin  = (const float*)d_in[3];
    const float* b_lin  = (const float*)d_in[4];
    const float* W_conv = (const float*)d_in[5];
    const float* b_conv = (const float*)d_in[6];
    const float* W_lin2 = (const float*)d_in[7];
    const float* b_lin2 = (const float*)d_in[8];
    const float* Wa     = (const float*)d_in[9];
    const float* ba     = (const float*)d_in[10];
    const float* Wx     = (const float*)d_in[11];
    const float* bx     = (const float*)d_in[12];
    const float* Lam    = (const float*)d_in[13];
    const float* W1     = (const float*)d_in[14];
    const float* b1     = (const float*)d_in[15];
    const float* W2     = (const float*)d_in[16];
    const float* b2     = (const float*)d_in[17];
    const float* W3     = (const float*)d_in[18];
    const float* b3     = (const float*)d_in[19];
    float* out = (float*)d_out;

    float *Acar, *Hcar, *carry;
    __half *res16, *Af, *Af2, *rt16, *g16, *Wf;
    cudaGetSymbolAddress((void**)&res16, g_res16);
    cudaGetSymbolAddress((void**)&Acar, g_Acar);
    cudaGetSymbolAddress((void**)&Hcar, g_Hcar);
    cudaGetSymbolAddress((void**)&carry, g_carry);
    cudaGetSymbolAddress((void**)&Af,   g_Af);
    cudaGetSymbolAddress((void**)&Af2,  g_Af2);
    cudaGetSymbolAddress((void**)&rt16, g_rt16);
    cudaGetSymbolAddress((void**)&g16,  g_g16);
    cudaGetSymbolAddress((void**)&Wf,   g_Wf);

    const int FGEMM_SMEM = 2 * F_STAGE + 1024;   // 66560
    cudaFuncSetAttribute(fgemm_kernel,
                         cudaFuncAttributeMaxDynamicSharedMemorySize, FGEMM_SMEM);
    cudaFuncSetAttribute(fgemm_dual_kernel,
                         cudaFuncAttributeMaxDynamicSharedMemorySize, FGEMM_SMEM);

    dim3 gg1(DDIM / 128, MROWS / 128);       // (8, 128)   singles
    dim3 ggd(DDIM / 64, MROWS / 128);        // (16, 128)  duals
    int scBlocks  = (NCHAIN / 4 * CHUNKS) / 256;      // 256
    const size_t WN = (size_t)DDIM * DDIM;

    const float* FZ = (const float*)nullptr;
    float* FZo = (float*)nullptr;
    __half* HZ = (__half*)nullptr;
    const __half* HZc = (const __half*)nullptr;

    // 0+1) prologue: Af = fp16(rmsnorm(x,g1)) AND convert all 8 weights
    //      slots: 0:W_lin 1:W_conv 2:Wa 3:Wx 4:W_lin2 5:W1 6:W2 7:W3
    prologue_kernel<<<8192, 256>>>(x, g1, Af,
                                   W_lin, W_conv, Wa, Wx, W_lin2, W1, W2, W3, Wf);
    // 2) lin(fp16 Af2) = xn @ W_lin^T + b_lin
    fgemm_kernel<<<gg1, 256, FGEMM_SMEM>>>(Af, Wf, b_lin, FZ, HZc, FZo, 0, Af2);
    // 3) rg(fp16 Af) = lin @ W_conv^T + b_conv
    fgemm_kernel<<<gg1, 256, FGEMM_SMEM>>>(Af2, Wf + WN, b_conv, FZ, HZc, FZo, 0, Af);
    // 4) dual GATE: rt16 = rg@Wa^T+ba (pre-act) ; g16 = sqrt(1-a^2)*sig(rg@Wx^T+bx)*rg
    fgemm_dual_kernel<<<ggd, 256, FGEMM_SMEM>>>(Af, Wf + 2 * WN, Wf + 3 * WN,
                                                ba, bx, 1, rt16, g16, Lam, Af);
    // 5-7) chunked scan (hl round-trip eliminated; scan3 recomputes local h)
    scan1_kernel<<<scBlocks, 256>>>(rt16, g16, Lam, Acar, Hcar);
    scan2_kernel<<<NCHAIN / 256, 256>>>(Acar, Hcar, carry);
    scan3_kernel<<<scBlocks, 256>>>(rt16, g16, carry, Lam, Af2);
    // 8) res16 = fp16( (gelu(lin)*h) @ W_lin2^T + b_lin2 + x )   (slot 4)
    fgemm_kernel<<<gg1, 256, FGEMM_SMEM>>>(Af2, Wf + 4 * WN, b_lin2, x, HZc, FZo, 1, res16);
    // 9) Af = fp16(rmsnorm(res16, g2))
    rmsnorm_h_kernel<<<MROWS / 4, 256>>>(res16, g2, Af);
    // 10) dual COMB: Af2 = gelu(sig(xm@W1^T+b1)) * (xm@W2^T+b2)   (slots 5,6)
    fgemm_dual_kernel<<<ggd, 256, FGEMM_SMEM>>>(Af, Wf + 5 * WN, Wf + 6 * WN,
                                                b1, b2, 0, Af2, HZ, FZ, HZc);
    // 12) out = combined @ W3^T + b3 + res16   (slot 7)
    fgemm_kernel<<<gg1, 256, FGEMM_SMEM>>>(Af2, Wf + 7 * WN, b3, FZ, res16, out, 2, HZ);

    (void)in_sizes; (void)n_in; (void)out_size;
}

// round 17
// speedup vs baseline: 1.2153x; 1.0649x over previous
#include <cuda_runtime.h>
#include <cuda_fp16.h>
#include <math.h>
#include <cstdint>

// Problem dims
#define MROWS 16384   // B*T = 4*4096
#define DDIM  1024
#define TLEN  4096
#define CHUNKS 64
#define CHLEN  (TLEN / CHUNKS)   // 64
#define NCHAIN 4096              // B * D

// ---------------- scratch (device globals; no allocation allowed) ----------
__device__ __half g_res16[MROWS * DDIM];
__device__ __half g_Af  [MROWS * DDIM];
__device__ __half g_Af2 [MROWS * DDIM];
__device__ __half g_rt16[MROWS * DDIM];
__device__ __half g_g16 [MROWS * DDIM];
__device__ __half g_Wf [8 * DDIM * DDIM];   // 8 weight slots
__device__ float g_la [DDIM];               // precomputed -log1p(exp(-Lam))
__device__ float g_Acar[NCHAIN * CHUNKS];
__device__ float g_Hcar[NCHAIN * CHUNKS];
__device__ float g_carry[NCHAIN * CHUNKS];

// ---------------- base-ISA tensor helpers ----------------------------------
__device__ __forceinline__ uint32_t smem_to_u32(const void* p) {
    uint32_t a;
    asm("{ .reg .u64 t; cvta.to.shared.u64 t, %1; cvt.u32.u64 %0, t; }"
        : "=r"(a) : "l"(p));
    return a;
}
__device__ __forceinline__ void cpasync16(uint32_t dst, const void* src) {
    asm volatile("cp.async.cg.shared.global [%0], [%1], 16;"
                 :: "r"(dst), "l"(src) : "memory");
}
#define CP_COMMIT() asm volatile("cp.async.commit_group;" ::: "memory")
#define CP_WAIT(n)  asm volatile("cp.async.wait_group %0;" :: "n"(n) : "memory")

__device__ __forceinline__ void ldsm4(uint32_t addr, uint32_t* r) {
    asm volatile("ldmatrix.sync.aligned.m8n8.x4.shared.b16 {%0,%1,%2,%3}, [%4];"
                 : "=r"(r[0]), "=r"(r[1]), "=r"(r[2]), "=r"(r[3]) : "r"(addr));
}
__device__ __forceinline__ void mma16816h(float* c, const uint32_t* a, const uint32_t* b) {
    asm volatile(
        "mma.sync.aligned.m16n8k16.row.col.f32.f16.f16.f32 "
        "{%0,%1,%2,%3}, {%4,%5,%6,%7}, {%8,%9}, {%0,%1,%2,%3};"
        : "+f"(c[0]), "+f"(c[1]), "+f"(c[2]), "+f"(c[3])
        : "r"(a[0]), "r"(a[1]), "r"(a[2]), "r"(a[3]), "r"(b[0]), "r"(b[1]));
}

// ---------------- math helpers ---------------------------------------------
__device__ __forceinline__ float gelu_exact(float x) {
    return 0.5f * x * (1.0f + erff(x * 0.70710678118654752440f));
}
__device__ __forceinline__ float fsig(float x) {
    return __fdividef(1.0f, 1.0f + __expf(-x));
}
__device__ __forceinline__ float h2lo(uint32_t u) {
    __half2 h = *(__half2*)&u;
    return __low2float(h);
}
__device__ __forceinline__ float h2hi(uint32_t u) {
    __half2 h = *(__half2*)&u;
    return __high2float(h);
}
__device__ __forceinline__ uint32_t pack2h(float a, float b) {
    __half2 h = __floats2half2_rn(a, b);
    return *(uint32_t*)&h;
}

// ---------------- prologue: rmsnorm(x,g1) + weight conv + la precompute ----
// grid.x = 8193: [0,4096) rmsnorm (4 rows each), [4096,8192) weight conv,
// block 8192 computes la[d] = -log1p(exp(-Lam[d])).
__global__ void prologue_kernel(const float* __restrict__ x, const float* __restrict__ g1,
                                __half* __restrict__ Af,
                                const float* __restrict__ w0, const float* __restrict__ w1,
                                const float* __restrict__ w2, const float* __restrict__ w3,
                                const float* __restrict__ w4, const float* __restrict__ w5,
                                const float* __restrict__ w6, const float* __restrict__ w7,
                                __half* __restrict__ Wf,
                                const float* __restrict__ Lam, float* __restrict__ la_buf) {
    int bx = blockIdx.x;
    int tid = threadIdx.x;
    if (bx < 4096) {
        int row0 = bx * 4;
        float4 v[4];
        #pragma unroll
        for (int j = 0; j < 4; j++)
            v[j] = ((const float4*)(x + (size_t)(row0 + j) * DDIM))[tid];
        float4 g = ((const float4*)g1)[tid];
        float ps[4];
        #pragma unroll
        for (int j = 0; j < 4; j++)
            ps[j] = v[j].x * v[j].x + v[j].y * v[j].y + v[j].z * v[j].z + v[j].w * v[j].w;
        #pragma unroll
        for (int j = 0; j < 4; j++)
            #pragma unroll
            for (int o = 16; o > 0; o >>= 1)
                ps[j] += __shfl_xor_sync(0xffffffffu, ps[j], o);
        __shared__ float sred[4][8];
        if ((tid & 31) == 0)
            #pragma unroll
            for (int j = 0; j < 4; j++) sred[j][tid >> 5] = ps[j];
        __syncthreads();
        float s[4];
        #pragma unroll
        for (int j = 0; j < 4; j++) {
            float total = 0.0f;
            #pragma unroll
            for (int i = 0; i < 8; i++) total += sred[j][i];
            s[j] = 32.0f / fmaxf(sqrtf(total), 1e-12f);
        }
        #pragma unroll
        for (int j = 0; j < 4; j++) {
            float o0 = v[j].x * s[j] * g.x, o1 = v[j].y * s[j] * g.y;
            float o2 = v[j].z * s[j] * g.z, o3 = v[j].w * s[j] * g.w;
            size_t base2 = (size_t)(row0 + j) * (DDIM / 2) + tid * 2;
            ((__half2*)Af)[base2]     = __floats2half2_rn(o0, o1);
            ((__half2*)Af)[base2 + 1] = __floats2half2_rn(o2, o3);
        }
    } else if (bx < 8192) {
        const float* srcs[8] = {w0, w1, w2, w3, w4, w5, w6, w7};
        int bxr = bx - 4096;
        int slot = bxr >> 9;
        const float* src = srcs[slot];
        __half* d = Wf + (size_t)slot * DDIM * DDIM;
        int i = ((bxr & 511) * 256 + tid) * 2;
        float4 v0 = ((const float4*)src)[i];
        float4 v1 = ((const float4*)src)[i + 1];
        ((__half2*)d)[2 * i]     = __floats2half2_rn(v0.x, v0.y);
        ((__half2*)d)[2 * i + 1] = __floats2half2_rn(v0.z, v0.w);
        ((__half2*)d)[2 * i + 2] = __floats2half2_rn(v1.x, v1.y);
        ((__half2*)d)[2 * i + 3] = __floats2half2_rn(v1.z, v1.w);
    } else {
        // la precompute (accurate): 256 threads x 4
        #pragma unroll
        for (int j = 0; j < 4; j++) {
            int d = tid * 4 + j;
            la_buf[d] = -log1pf(expf(-Lam[d]));
        }
    }
}

// ---------------- fp16 1-term mma.sync GEMM, BN=128, 2-stage ---------------
// doAdd: 0 = none, 1 = += addp (fp32), 2 = += addpH (fp16)
#define F_TILE_A 16384               // 128 x 64 fp16
#define F_TILE_B 16384               // 128 x 64 fp16
#define F_STAGE  32768
#define NCHUNK (DDIM / 64)           // 16

__device__ __forceinline__ uint32_t swaddr(uint32_t tile, uint32_t row, uint32_t kb) {
    uint32_t off = row * 128u + kb;
    return tile + (off ^ ((off >> 3) & 0x70u));
}

__global__ void __launch_bounds__(256, 2)
fgemm_kernel(const __half* __restrict__ Af, const __half* __restrict__ Bf,
             const float* __restrict__ bias,
             const float* __restrict__ addp, const __half* __restrict__ addpH,
             float* __restrict__ C, int doAdd,
             __half* __restrict__ Sf) {
    extern __shared__ __align__(1024) char smem_raw[];
    uint32_t smem0 = smem_to_u32(smem_raw);
    uint32_t tbase = (smem0 + 1023u) & ~1023u;

    int tid = threadIdx.x;
    int wid = tid >> 5;
    int lane = tid & 31;
    int m0 = blockIdx.y * 128;
    int n0 = blockIdx.x * 128;

    int row_base = tid >> 3;        // 0..31
    int col = tid & 7;
    const char* srcb[8];
    uint32_t stsoff[8];
    {
        const char* aB = (const char*)(Af + (size_t)m0 * DDIM);
        const char* bB = (const char*)(Bf + (size_t)n0 * DDIM);
        #pragma unroll
        for (int i = 0; i < 4; i++) {
            uint32_t rr = (uint32_t)row_base + 32u * i;
            srcb[i] = aB + (size_t)rr * 2048 + col * 16;
            uint32_t off = rr * 128u + (uint32_t)col * 16u;
            stsoff[i] = off ^ ((off >> 3) & 0x70u);
        }
        #pragma unroll
        for (int i = 4; i < 8; i++) {
            uint32_t rr = (uint32_t)row_base + 32u * (i - 4);
            srcb[i] = bB + (size_t)rr * 2048 + col * 16;
            uint32_t off = rr * 128u + (uint32_t)col * 16u;
            stsoff[i] = F_TILE_A + (off ^ ((off >> 3) & 0x70u));
        }
    }

    #define F_ISSUE(buf, chunk) do { \
        uint32_t db_ = tbase + (uint32_t)(buf) * F_STAGE; \
        _Pragma("unroll") \
        for (int i_ = 0; i_ < 8; i_++) \
            cpasync16(db_ + stsoff[i_], srcb[i_] + (size_t)(chunk) * 128); \
        CP_COMMIT(); \
    } while (0)

    int warp_m = wid & 3;
    int warp_n = wid >> 2;          // 0..1
    uint32_t ar  = (uint32_t)((lane & 7) + ((lane >> 3) & 1) * 8);
    uint32_t akb = (uint32_t)(((lane >> 4) & 1) * 16);
    uint32_t br  = (uint32_t)((lane & 7) + ((lane >> 4) & 1) * 8);
    uint32_t bkb = (uint32_t)(((lane >> 3) & 1) * 16);

    float acc[2][8][4];
    #pragma unroll
    for (int i = 0; i < 2; i++)
        #pragma unroll
        for (int j = 0; j < 8; j++)
            #pragma unroll
            for (int q = 0; q < 4; q++) acc[i][j][q] = 0.0f;

    F_ISSUE(0, 0);

    for (int c = 0; c < NCHUNK; c++) {
        CP_WAIT(0);
        __syncthreads();
        if (c + 1 < NCHUNK) F_ISSUE((c + 1) & 1, c + 1);

        uint32_t sb = tbase + (uint32_t)(c & 1) * F_STAGE;
        uint32_t tAf = sb;
        uint32_t tBf = sb + F_TILE_A;

        #pragma unroll
        for (int k16 = 0; k16 < 4; k16++) {
            uint32_t kb = (uint32_t)k16 * 32u;
            uint32_t af[2][4], bf[4][4];
            #pragma unroll
            for (int mt = 0; mt < 2; mt++)
                ldsm4(swaddr(tAf, (uint32_t)(warp_m * 32 + mt * 16) + ar, kb + akb), af[mt]);
            #pragma unroll
            for (int p = 0; p < 4; p++)
                ldsm4(swaddr(tBf, (uint32_t)(warp_n * 64 + p * 16) + br, kb + bkb), bf[p]);
            #pragma unroll
            for (int mt = 0; mt < 2; mt++)
                #pragma unroll
                for (int p = 0; p < 4; p++) {
                    mma16816h(acc[mt][2 * p],     af[mt], &bf[p][0]);
                    mma16816h(acc[mt][2 * p + 1], af[mt], &bf[p][2]);
                }
        }
    }

    int lm = lane >> 2;
    int lc = (lane & 3) * 2;
    int cm = m0 + warp_m * 32;
    int cn = n0 + warp_n * 64;
    #pragma unroll
    for (int mt = 0; mt < 2; mt++) {
        #pragma unroll
        for (int nt = 0; nt < 8; nt++) {
            int r0 = cm + mt * 16 + lm;
            int cc = cn + nt * 8 + lc;
            float2 bv = *(const float2*)&bias[cc];
            float* a = acc[mt][nt];
            float2 o0 = make_float2(a[0] + bv.x, a[1] + bv.y);
            float2 o1 = make_float2(a[2] + bv.x, a[3] + bv.y);
            size_t off0 = (size_t)r0 * DDIM + cc;
            size_t off1 = (size_t)(r0 + 8) * DDIM + cc;
            if (doAdd == 1) {
                float2 q0 = *(const float2*)(addp + off0);
                float2 q1 = *(const float2*)(addp + off1);
                o0.x += q0.x; o0.y += q0.y;
                o1.x += q1.x; o1.y += q1.y;
            } else if (doAdd == 2) {
                __half2 q0 = *(const __half2*)(addpH + off0);
                __half2 q1 = *(const __half2*)(addpH + off1);
                o0.x += __low2float(q0); o0.y += __high2float(q0);
                o1.x += __low2float(q1); o1.y += __high2float(q1);
            }
            if (C) {
                *(float2*)(C + off0) = o0;
                *(float2*)(C + off1) = o1;
            }
            if (Sf) {
                *(__half2*)(Sf + off0) = __floats2half2_rn(o0.x, o0.y);
                *(__half2*)(Sf + off1) = __floats2half2_rn(o1.x, o1.y);
            }
        }
    }
}

// ---------------- dual-weight fused GEMM -----------------------------------
// mode 0 (COMB): O1 <- fp16( gelu(sigmoid(v1)) * v2 )
// mode 1 (GATE): O1 <- fp16(v1) ; O2 <- fp16( sqrt(1-a^2)*sigmoid(v2)*rg ),
//                a = __expf(la * sigmoid(v1) / 8), la preloaded from la_buf.
#define D_TILE_B 8192

__global__ void __launch_bounds__(256, 2)
fgemm_dual_kernel(const __half* __restrict__ Af,
                  const __half* __restrict__ B1, const __half* __restrict__ B2,
                  const float* __restrict__ bias1, const float* __restrict__ bias2,
                  int mode,
                  __half* __restrict__ O1, __half* __restrict__ O2,
                  const float* __restrict__ la_buf, const __half* __restrict__ rgbuf) {
    extern __shared__ __align__(1024) char smem_raw[];
    uint32_t smem0 = smem_to_u32(smem_raw);
    uint32_t tbase = (smem0 + 1023u) & ~1023u;

    int tid = threadIdx.x;
    int wid = tid >> 5;
    int lane = tid & 31;
    int m0 = blockIdx.y * 128;
    int n0 = blockIdx.x * 64;

    int row_base = tid >> 3;        // 0..31
    int col = tid & 7;
    const char* srcb[8];
    uint32_t stsoff[8];
    {
        const char* aB  = (const char*)(Af + (size_t)m0 * DDIM);
        const char* b1B = (const char*)(B1 + (size_t)n0 * DDIM);
        const char* b2B = (const char*)(B2 + (size_t)n0 * DDIM);
        #pragma unroll
        for (int i = 0; i < 4; i++) {
            uint32_t rr = (uint32_t)row_base + 32u * i;
            srcb[i] = aB + (size_t)rr * 2048 + col * 16;
            uint32_t off = rr * 128u + (uint32_t)col * 16u;
            stsoff[i] = off ^ ((off >> 3) & 0x70u);
        }
        #pragma unroll
        for (int i = 4; i < 6; i++) {
            uint32_t rr = (uint32_t)row_base + 32u * (i - 4);
            srcb[i] = b1B + (size_t)rr * 2048 + col * 16;
            uint32_t off = rr * 128u + (uint32_t)col * 16u;
            stsoff[i] = F_TILE_A + (off ^ ((off >> 3) & 0x70u));
        }
        #pragma unroll
        for (int i = 6; i < 8; i++) {
            uint32_t rr = (uint32_t)row_base + 32u * (i - 6);
            srcb[i] = b2B + (size_t)rr * 2048 + col * 16;
            uint32_t off = rr * 128u + (uint32_t)col * 16u;
            stsoff[i] = F_TILE_A + D_TILE_B + (off ^ ((off >> 3) & 0x70u));
        }
    }

    #define D_ISSUE(buf, chunk) do { \
        uint32_t db_ = tbase + (uint32_t)(buf) * F_STAGE; \
        _Pragma("unroll") \
        for (int i_ = 0; i_ < 8; i_++) \
            cpasync16(db_ + stsoff[i_], srcb[i_] + (size_t)(chunk) * 128); \
        CP_COMMIT(); \
    } while (0)

    int warp_m = wid & 3;
    int warp_n = wid >> 2;          // 0..1 (32-col halves)
    uint32_t ar  = (uint32_t)((lane & 7) + ((lane >> 3) & 1) * 8);
    uint32_t akb = (uint32_t)(((lane >> 4) & 1) * 16);
    uint32_t br  = (uint32_t)((lane & 7) + ((lane >> 4) & 1) * 8);
    uint32_t bkb = (uint32_t)(((lane >> 3) & 1) * 16);

    float acc1[2][4][4], acc2[2][4][4];
    #pragma unroll
    for (int i = 0; i < 2; i++)
        #pragma unroll
        for (int j = 0; j < 4; j++)
            #pragma unroll
            for (int q = 0; q < 4; q++) { acc1[i][j][q] = 0.0f; acc2[i][j][q] = 0.0f; }

    D_ISSUE(0, 0);

    for (int c = 0; c < NCHUNK; c++) {
        CP_WAIT(0);
        __syncthreads();
        if (c + 1 < NCHUNK) D_ISSUE((c + 1) & 1, c + 1);

        uint32_t sb = tbase + (uint32_t)(c & 1) * F_STAGE;
        uint32_t tAf = sb;
        uint32_t tB1 = sb + F_TILE_A;
        uint32_t tB2 = sb + F_TILE_A + D_TILE_B;

        #pragma unroll
        for (int k16 = 0; k16 < 4; k16++) {
            uint32_t kb = (uint32_t)k16 * 32u;
            uint32_t af[2][4], bf1[2][4], bf2[2][4];
            #pragma unroll
            for (int mt = 0; mt < 2; mt++)
                ldsm4(swaddr(tAf, (uint32_t)(warp_m * 32 + mt * 16) + ar, kb + akb), af[mt]);
            #pragma unroll
            for (int p = 0; p < 2; p++)
                ldsm4(swaddr(tB1, (uint32_t)(warp_n * 32 + p * 16) + br, kb + bkb), bf1[p]);
            #pragma unroll
            for (int p = 0; p < 2; p++)
                ldsm4(swaddr(tB2, (uint32_t)(warp_n * 32 + p * 16) + br, kb + bkb), bf2[p]);
            #pragma unroll
            for (int mt = 0; mt < 2; mt++)
                #pragma unroll
                for (int p = 0; p < 2; p++) {
                    mma16816h(acc1[mt][2 * p],     af[mt], &bf1[p][0]);
                    mma16816h(acc1[mt][2 * p + 1], af[mt], &bf1[p][2]);
                    mma16816h(acc2[mt][2 * p],     af[mt], &bf2[p][0]);
                    mma16816h(acc2[mt][2 * p + 1], af[mt], &bf2[p][2]);
                }
        }
    }

    int lm = lane >> 2;
    int lc = (lane & 3) * 2;
    int cm = m0 + warp_m * 32;
    int cn = n0 + warp_n * 32;
    #pragma unroll
    for (int mt = 0; mt < 2; mt++) {
        #pragma unroll
        for (int nt = 0; nt < 4; nt++) {
            int r0 = cm + mt * 16 + lm;
            int cc = cn + nt * 8 + lc;
            float2 b1v = *(const float2*)&bias1[cc];
            float2 b2v = *(const float2*)&bias2[cc];
            float* a1 = acc1[mt][nt];
            float* a2 = acc2[mt][nt];
            size_t off0 = (size_t)r0 * DDIM + cc;
            size_t off1 = (size_t)(r0 + 8) * DDIM + cc;
            float v1r0x = a1[0] + b1v.x, v1r0y = a1[1] + b1v.y;
            float v1r1x = a1[2] + b1v.x, v1r1y = a1[3] + b1v.y;
            float v2r0x = a2[0] + b2v.x, v2r0y = a2[1] + b2v.y;
            float v2r1x = a2[2] + b2v.x, v2r1y = a2[3] + b2v.y;
            if (mode == 0) {
                *(__half2*)(O1 + off0) = __floats2half2_rn(
                    gelu_exact(fsig(v1r0x)) * v2r0x,
                    gelu_exact(fsig(v1r0y)) * v2r0y);
                *(__half2*)(O1 + off1) = __floats2half2_rn(
                    gelu_exact(fsig(v1r1x)) * v2r1x,
                    gelu_exact(fsig(v1r1y)) * v2r1y);
            } else {
                float2 la = *(const float2*)&la_buf[cc];
                __half2 rg0 = *(const __half2*)(rgbuf + off0);
                __half2 rg1 = *(const __half2*)(rgbuf + off1);
                float a0 = __expf(la.x * fsig(v1r0x) * 0.125f);
                float a1_ = __expf(la.y * fsig(v1r0y) * 0.125f);
                float a2_ = __expf(la.x * fsig(v1r1x) * 0.125f);
                float a3_ = __expf(la.y * fsig(v1r1y) * 0.125f);
                float g0 = sqrtf(fmaxf(1.0f - a0 * a0, 0.0f)) * fsig(v2r0x) * __low2float(rg0);
                float g1 = sqrtf(fmaxf(1.0f - a1_ * a1_, 0.0f)) * fsig(v2r0y) * __high2float(rg0);
                float g2 = sqrtf(fmaxf(1.0f - a2_ * a2_, 0.0f)) * fsig(v2r1x) * __low2float(rg1);
                float g3 = sqrtf(fmaxf(1.0f - a3_ * a3_, 0.0f)) * fsig(v2r1y) * __high2float(rg1);
                *(__half2*)(O1 + off0) = __floats2half2_rn(v1r0x, v1r0y);
                *(__half2*)(O1 + off1) = __floats2half2_rn(v1r1x, v1r1y);
                *(__half2*)(O2 + off0) = __floats2half2_rn(g0, g1);
                *(__half2*)(O2 + off1) = __floats2half2_rn(g2, g3);
            }
        }
    }
}

// ---------------- rmsnorm (fp16 in) -> fp16, 4 rows per block --------------
__global__ void rmsnorm_h_kernel(const __half* __restrict__ x16,
                                 const float* __restrict__ gw,
                                 __half* __restrict__ Sf) {
    int row0 = blockIdx.x * 4;
    int tid = threadIdx.x;
    uint2 v[4];
    #pragma unroll
    for (int j = 0; j < 4; j++)
        v[j] = ((const uint2*)(x16 + (size_t)(row0 + j) * DDIM))[tid];
    float4 g = ((const float4*)gw)[tid];

    float f[4][4];
    float ps[4];
    #pragma unroll
    for (int j = 0; j < 4; j++) {
        f[j][0] = h2lo(v[j].x); f[j][1] = h2hi(v[j].x);
        f[j][2] = h2lo(v[j].y); f[j][3] = h2hi(v[j].y);
        ps[j] = f[j][0] * f[j][0] + f[j][1] * f[j][1]
              + f[j][2] * f[j][2] + f[j][3] * f[j][3];
    }
    #pragma unroll
    for (int j = 0; j < 4; j++)
        #pragma unroll
        for (int o = 16; o > 0; o >>= 1)
            ps[j] += __shfl_xor_sync(0xffffffffu, ps[j], o);

    __shared__ float sred[4][8];
    if ((tid & 31) == 0)
        #pragma unroll
        for (int j = 0; j < 4; j++) sred[j][tid >> 5] = ps[j];
    __syncthreads();
    float s[4];
    #pragma unroll
    for (int j = 0; j < 4; j++) {
        float total = 0.0f;
        #pragma unroll
        for (int i = 0; i < 8; i++) total += sred[j][i];
        s[j] = 32.0f / fmaxf(sqrtf(total), 1e-12f);
    }
    #pragma unroll
    for (int j = 0; j < 4; j++) {
        float o0 = f[j][0] * s[j] * g.x, o1 = f[j][1] * s[j] * g.y;
        float o2 = f[j][2] * s[j] * g.z, o3 = f[j][3] * s[j] * g.w;
        size_t base2 = (size_t)(row0 + j) * (DDIM / 2) + tid * 2;
        ((__half2*)Sf)[base2]     = __floats2half2_rn(o0, o1);
        ((__half2*)Sf)[base2 + 1] = __floats2half2_rn(o2, o3);
    }
}

// ---------------- chunked RG-LRU scan (4 chains/thread, uint2) -------------
// pass 1: chunk aggregates only (no hl store)
__global__ void scan1_kernel(const __half* __restrict__ rt, const __half* __restrict__ gt,
                             const float* __restrict__ la_buf,
                             float* __restrict__ Acar, float* __restrict__ Hcar) {
    int i = blockIdx.x * 256 + threadIdx.x;     // 0 .. 65535 (quads x chunks)
    int q = i & 1023;
    int chunk = i >> 10;
    int b = q >> 8;
    int dq = q & 255;
    size_t base4 = (((size_t)b * TLEN + (size_t)chunk * CHLEN) * DDIM) / 4 + dq;
    float4 lav = *(const float4*)&la_buf[4 * dq];
    float la[4] = {lav.x, lav.y, lav.z, lav.w};
    float h[4] = {0, 0, 0, 0}, P[4] = {1, 1, 1, 1};
    const uint2* rt4 = (const uint2*)rt;
    const uint2* gt4 = (const uint2*)gt;
    #pragma unroll 4
    for (int t = 0; t < CHLEN; t++) {
        size_t a_ = base4 + (size_t)t * (DDIM / 4);
        uint2 rv = rt4[a_], gv = gt4[a_];
        float rr[4] = {h2lo(rv.x), h2hi(rv.x), h2lo(rv.y), h2hi(rv.y)};
        float gg[4] = {h2lo(gv.x), h2hi(gv.x), h2lo(gv.y), h2hi(gv.y)};
        #pragma unroll
        for (int j = 0; j < 4; j++) {
            float a = __expf(la[j] * fsig(rr[j]) * 0.125f);
            h[j] = fmaf(a, h[j], gg[j]);
            P[j] *= a;
        }
    }
    int chain = b * DDIM + 4 * dq;
    #pragma unroll
    for (int j = 0; j < 4; j++) {
        Acar[chunk * NCHAIN + chain + j] = P[j];
        Hcar[chunk * NCHAIN + chain + j] = h[j];
    }
}

// pass 2: serial scan over chunk aggregates (per chain)
__global__ void scan2_kernel(const float* __restrict__ Acar, const float* __restrict__ Hcar,
                             float* __restrict__ carry) {
    int chain = blockIdx.x * 256 + threadIdx.x;   // 0..4095
    float h = 0.0f;
    #pragma unroll
    for (int c = 0; c < CHUNKS; c++) {
        int idx = c * NCHAIN + chain;
        carry[idx] = h;
        h = fmaf(Acar[idx], h, Hcar[idx]);
    }
}

// pass 3: recompute local scan + carry, fused gelu(lin)*h, fp16 in-place
__global__ void scan3_kernel(const __half* __restrict__ rt, const __half* __restrict__ gt,
                             const float* __restrict__ carry,
                             const float* __restrict__ la_buf,
                             __half* __restrict__ linSf) {
    int i = blockIdx.x * 256 + threadIdx.x;     // 0 .. 65535
    int q = i & 1023;
    int chunk = i >> 10;
    int b = q >> 8;
    int dq = q & 255;
    size_t base4 = (((size_t)b * TLEN + (size_t)chunk * CHLEN) * DDIM) / 4 + dq;
    float4 lav = *(const float4*)&la_buf[4 * dq];
    float la[4] = {lav.x, lav.y, lav.z, lav.w};
    int chain = b * DDIM + 4 * dq;
    float cin[4], P[4] = {1, 1, 1, 1}, hloc[4] = {0, 0, 0, 0};
    #pragma unroll
    for (int j = 0; j < 4; j++) cin[j] = carry[chunk * NCHAIN + chain + j];
    const uint2* rt4 = (const uint2*)rt;
    const uint2* gt4 = (const uint2*)gt;
    uint2* ls4 = (uint2*)linSf;
    #pragma unroll 4
    for (int t = 0; t < CHLEN; t++) {
        size_t a_ = base4 + (size_t)t * (DDIM / 4);
        uint2 rv = rt4[a_], gv = gt4[a_], lv = ls4[a_];
        float rr[4] = {h2lo(rv.x), h2hi(rv.x), h2lo(rv.y), h2hi(rv.y)};
        float gg[4] = {h2lo(gv.x), h2hi(gv.x), h2lo(gv.y), h2hi(gv.y)};
        float ll[4] = {h2lo(lv.x), h2hi(lv.x), h2lo(lv.y), h2hi(lv.y)};
        float oo[4];
        #pragma unroll
        for (int j = 0; j < 4; j++) {
            float a = __expf(la[j] * fsig(rr[j]) * 0.125f);
            hloc[j] = fmaf(a, hloc[j], gg[j]);
            P[j] *= a;
            float h = fmaf(P[j], cin[j], hloc[j]);
            oo[j] = gelu_exact(ll[j]) * h;
        }
        uint2 o;
        o.x = pack2h(oo[0], oo[1]);
        o.y = pack2h(oo[2], oo[3]);
        ls4[a_] = o;
    }
}

// ---------------- launch ---------------------------------------------------
extern "C" void kernel_launch(void* const* d_in, const int* in_sizes, int n_in,
                              void* d_out, int out_size) {
    const float* x      = (const float*)d_in[0];
    const float* g1     = (const float*)d_in[1];
    const float* g2     = (const float*)d_in[2];
    const float* W_lin  = (const float*)d_in[3];
    const float* b_lin  = (const float*)d_in[4];
    const float* W_conv = (const float*)d_in[5];
    const float* b_conv = (const float*)d_in[6];
    const float* W_lin2 = (const float*)d_in[7];
    const float* b_lin2 = (const float*)d_in[8];
    const float* Wa     = (const float*)d_in[9];
    const float* ba     = (const float*)d_in[10];
    const float* Wx     = (const float*)d_in[11];
    const float* bx     = (const float*)d_in[12];
    const float* Lam    = (const float*)d_in[13];
    const float* W1     = (const float*)d_in[14];
    const float* b1     = (const float*)d_in[15];
    const float* W2     = (const float*)d_in[16];
    const float* b2     = (const float*)d_in[17];
    const float* W3     = (const float*)d_in[18];
    const float* b3     = (const float*)d_in[19];
    float* out = (float*)d_out;

    float *Acar, *Hcar, *carry, *la_buf;
    __half *res16, *Af, *Af2, *rt16, *g16, *Wf;
    cudaGetSymbolAddress((void**)&res16, g_res16);
    cudaGetSymbolAddress((void**)&Acar, g_Acar);
    cudaGetSymbolAddress((void**)&Hcar, g_Hcar);
    cudaGetSymbolAddress((void**)&carry, g_carry);
    cudaGetSymbolAddress((void**)&la_buf, g_la);
    cudaGetSymbolAddress((void**)&Af,   g_Af);
    cudaGetSymbolAddress((void**)&Af2,  g_Af2);
    cudaGetSymbolAddress((void**)&rt16, g_rt16);
    cudaGetSymbolAddress((void**)&g16,  g_g16);
    cudaGetSymbolAddress((void**)&Wf,   g_Wf);

    const int FGEMM_SMEM = 2 * F_STAGE + 1024;   // 66560
    cudaFuncSetAttribute(fgemm_kernel,
                         cudaFuncAttributeMaxDynamicSharedMemorySize, FGEMM_SMEM);
    cudaFuncSetAttribute(fgemm_dual_kernel,
                         cudaFuncAttributeMaxDynamicSharedMemorySize, FGEMM_SMEM);

    dim3 gg1(DDIM / 128, MROWS / 128);       // (8, 128)   singles
    dim3 ggd(DDIM / 64, MROWS / 128);        // (16, 128)  duals
    int scBlocks  = (NCHAIN / 4 * CHUNKS) / 256;      // 256
    const size_t WN = (size_t)DDIM * DDIM;

    const float* FZ = (const float*)nullptr;
    float* FZo = (float*)nullptr;
    __half* HZ = (__half*)nullptr;
    const __half* HZc = (const __half*)nullptr;

    // 0+1) prologue: rmsnorm(x,g1) + 8 weight conversions + la precompute
    prologue_kernel<<<8193, 256>>>(x, g1, Af,
                                   W_lin, W_conv, Wa, Wx, W_lin2, W1, W2, W3, Wf,
                                   Lam, la_buf);
    // 2) lin(fp16 Af2) = xn @ W_lin^T + b_lin
    fgemm_kernel<<<gg1, 256, FGEMM_SMEM>>>(Af, Wf, b_lin, FZ, HZc, FZo, 0, Af2);
    // 3) rg(fp16 Af) = lin @ W_conv^T + b_conv
    fgemm_kernel<<<gg1, 256, FGEMM_SMEM>>>(Af2, Wf + WN, b_conv, FZ, HZc, FZo, 0, Af);
    // 4) dual GATE: rt16 = rg@Wa^T+ba (pre-act) ; g16 = sqrt(1-a^2)*sig(rg@Wx^T+bx)*rg
    fgemm_dual_kernel<<<ggd, 256, FGEMM_SMEM>>>(Af, Wf + 2 * WN, Wf + 3 * WN,
                                                ba, bx, 1, rt16, g16, la_buf, Af);
    // 5-7) chunked scan
    scan1_kernel<<<scBlocks, 256>>>(rt16, g16, la_buf, Acar, Hcar);
    scan2_kernel<<<NCHAIN / 256, 256>>>(Acar, Hcar, carry);
    scan3_kernel<<<scBlocks, 256>>>(rt16, g16, carry, la_buf, Af2);
    // 8) res16 = fp16( (gelu(lin)*h) @ W_lin2^T + b_lin2 + x )   (slot 4)
    fgemm_kernel<<<gg1, 256, FGEMM_SMEM>>>(Af2, Wf + 4 * WN, b_lin2, x, HZc, FZo, 1, res16);
    // 9) Af = fp16(rmsnorm(res16, g2))
    rmsnorm_h_kernel<<<MROWS / 4, 256>>>(res16, g2, Af);
    // 10) dual COMB: Af2 = gelu(sig(xm@W1^T+b1)) * (xm@W2^T+b2)   (slots 5,6)
    fgemm_dual_kernel<<<ggd, 256, FGEMM_SMEM>>>(Af, Wf + 5 * WN, Wf + 6 * WN,
                                                b1, b2, 0, Af2, HZ, la_buf, HZc);
    // 12) out = combined @ W3^T + b3 + res16   (slot 7)
    fgemm_kernel<<<gg1, 256, FGEMM_SMEM>>>(Af2, Wf + 7 * WN, b3, FZ, res16, out, 2, HZ);

    (void)in_sizes; (void)n_in; (void)out_size;
}